// round 8
// baseline (speedup 1.0000x reference)
#include <cuda_runtime.h>
#include <cuda_fp16.h>
#include <cstdint>
#include <math.h>

// Problem constants (fixed by the dataset)
#define N0 30000
#define N1 50000
#define N2 20000
#define NTOT 100000
#define NE 1600000
#define NR 6
#define RN (NR * NTOT)

// ---------------------------------------------------------------------------
// Scratch (static __device__ globals; allocation-free per harness rules)
// ---------------------------------------------------------------------------
__device__ unsigned g_xbh[(size_t)NTOT * 64];  // packed hi: proj output, K=128 (25.6MB)
__device__ unsigned g_xbl[(size_t)NTOT * 64];  // packed lo
__device__ float g_xt1[(size_t)NTOT * 384];    // layer1 per-relation transform
__device__ float g_agg1[(size_t)NTOT * 64];    // layer1 accumulator / h1
__device__ float g_xt2[(size_t)NTOT * 96];     // layer2 per-relation transform
__device__ float g_agg2[(size_t)NTOT * 16];    // layer2 accumulator / h2
__device__ int   g_cnt[RN];
__device__ float g_inv[RN];
__device__ float g_W1[448 * 128];              // fp32 [n][k] (intermediate)
__device__ float g_W2[112 * 64];
// packed weights (hi/lo half2 words, permuted fragment layout)
__device__ unsigned g_w0h[128 * 128], g_w0l[128 * 128];   // lin_w0: 128x256
__device__ unsigned g_w1h[128 * 256], g_w1l[128 * 256];   // lin_w1: 128x512
__device__ unsigned g_w2h[128 * 64],  g_w2l[128 * 64];    // lin_w2: 128x128
__device__ unsigned g_W1h[448 * 64],  g_W1l[448 * 64];    // W1: 448x128
__device__ unsigned g_W2h[112 * 32],  g_W2l[112 * 32];    // W2: 112x64

// permuted half2-word index within a 32-col k-tile (kk even, in [0,32))
__device__ __forceinline__ int permw(int kk) {
    int c = kk >> 2;
    int idx0 = 8 * (c & 1) + 2 * (c >> 2) + ((c >> 1) & 1);
    return idx0 + ((kk >> 1) & 1) * 4;
}

// ---------------------------------------------------------------------------
// Small helper kernels
// ---------------------------------------------------------------------------
__global__ void zero_cnt_kernel() {
    int i = blockIdx.x * blockDim.x + threadIdx.x;
    if (i < RN) g_cnt[i] = 0;
}

__global__ void count_kernel(const int* __restrict__ dst, const int* __restrict__ et) {
    int e = blockIdx.x * blockDim.x + threadIdx.x;
    if (e < NE) atomicAdd(&g_cnt[et[e] * NTOT + dst[e]], 1);
}

__global__ void inv_kernel() {
    int i = blockIdx.x * blockDim.x + threadIdx.x;
    if (i < RN) {
        int c = g_cnt[i];
        g_inv[i] = 1.0f / (float)(c > 1 ? c : 1);
    }
}

__global__ void build_w1(const float* __restrict__ comp1, const float* __restrict__ bases1,
                         const float* __restrict__ root1) {
    int idx = blockIdx.x * blockDim.x + threadIdx.x;
    if (idx >= 448 * 128) return;
    int n = idx >> 7, k = idx & 127;
    float v;
    if (n < 384) {
        int r = n >> 6, o = n & 63;
        v = 0.0f;
        for (int b = 0; b < 30; b++)
            v += comp1[r * 30 + b] * bases1[((size_t)b * 128 + k) * 64 + o];
    } else {
        v = root1[k * 64 + (n - 384)];
    }
    g_W1[idx] = v;
}

__global__ void build_w2(const float* __restrict__ comp2, const float* __restrict__ bases2,
                         const float* __restrict__ root2) {
    int idx = blockIdx.x * blockDim.x + threadIdx.x;
    if (idx >= 112 * 64) return;
    int n = idx >> 6, k = idx & 63;
    float v;
    if (n < 96) {
        int r = n >> 4, o = n & 15;
        v = 0.0f;
        for (int b = 0; b < 30; b++)
            v += comp2[r * 30 + b] * bases2[((size_t)b * 64 + k) * 16 + o];
    } else {
        v = root2[k * 16 + (n - 96)];
    }
    g_W2[idx] = v;
}

// fp32 [Nrows][K] -> packed hi/lo half2 words in permuted fragment layout
__global__ void splitpack(const float* __restrict__ src, unsigned* __restrict__ hi,
                          unsigned* __restrict__ lo, int Nrows, int K) {
    int w = blockIdx.x * blockDim.x + threadIdx.x;
    int wpr = K >> 1;
    if (w >= Nrows * wpr) return;
    int row = w / wpr, kp = w - row * wpr;
    int k = kp * 2;
    float v0 = src[(size_t)row * K + k];
    float v1 = src[(size_t)row * K + k + 1];
    __half h0 = __float2half_rn(v0), h1 = __float2half_rn(v1);
    __half l0 = __float2half_rn(v0 - __half2float(h0));
    __half l1 = __float2half_rn(v1 - __half2float(h1));
    __half2 hh = __halves2half2(h0, h1);
    __half2 ll = __halves2half2(l0, l1);
    int widx = row * wpr + ((k >> 5) << 4) + permw(k & 31);
    hi[widx] = *(unsigned*)&hh;
    lo[widx] = *(unsigned*)&ll;
}

// ---------------------------------------------------------------------------
// FP16x3 split-precision tensor-core GEMM core (templated).
//   C[m,n] = sum_k A[m,k]*Bw[n,k]; a*b ~= ahi*bhi + ahi*blo + alo*bhi.
// 256 threads = 8 warps, 32x32 warptile: (TBM/32) m-warps x (TBN/32) n-warps.
// B always pre-packed; A either fp32 (on-the-fly split) or pre-packed.
// EPI: 0 = fp32 split outputs C1/C2 (+bias), 1 = packed hi/lo output (+bias b1).
// ---------------------------------------------------------------------------
__device__ __forceinline__ void mma_fp16(float* c, unsigned a0, unsigned a1,
                                         unsigned a2, unsigned a3,
                                         unsigned b0, unsigned b1) {
    asm volatile(
        "mma.sync.aligned.m16n8k16.row.col.f32.f16.f16.f32 "
        "{%0,%1,%2,%3}, {%4,%5,%6,%7}, {%8,%9}, {%0,%1,%2,%3};"
        : "+f"(c[0]), "+f"(c[1]), "+f"(c[2]), "+f"(c[3])
        : "r"(a0), "r"(a1), "r"(a2), "r"(a3), "r"(b0), "r"(b1));
}

__device__ __forceinline__ void mma_x3(float* c,
                                       const uint4& ah0, const uint4& ah1,
                                       const uint4& al0, const uint4& al1,
                                       const uint4& bh,  const uint4& bl) {
    mma_fp16(c, ah0.x, ah1.x, ah0.y, ah1.y, bh.x, bh.y);
    mma_fp16(c, ah0.x, ah1.x, ah0.y, ah1.y, bl.x, bl.y);
    mma_fp16(c, al0.x, al1.x, al0.y, al1.y, bh.x, bh.y);
    mma_fp16(c, ah0.z, ah1.z, ah0.w, ah1.w, bh.z, bh.w);
    mma_fp16(c, ah0.z, ah1.z, ah0.w, ah1.w, bl.z, bl.w);
    mma_fp16(c, al0.z, al1.z, al0.w, al1.w, bh.z, bh.w);
}

__device__ __forceinline__ void split_store(unsigned* hi, unsigned* lo,
                                            int row, int c, float4 v) {
    __half hx0 = __float2half_rn(v.x);
    __half hx1 = __float2half_rn(v.y);
    __half hx2 = __float2half_rn(v.z);
    __half hx3 = __float2half_rn(v.w);
    __half lx0 = __float2half_rn(v.x - __half2float(hx0));
    __half lx1 = __float2half_rn(v.y - __half2float(hx1));
    __half lx2 = __float2half_rn(v.z - __half2float(hx2));
    __half lx3 = __float2half_rn(v.w - __half2float(hx3));
    int idx0 = 8 * (c & 1) + 2 * (c >> 2) + ((c >> 1) & 1);
    __half2 h01 = __halves2half2(hx0, hx1);
    __half2 h23 = __halves2half2(hx2, hx3);
    __half2 l01 = __halves2half2(lx0, lx1);
    __half2 l23 = __halves2half2(lx2, lx3);
    hi[row * 16 + idx0]     = *(unsigned*)&h01;
    hi[row * 16 + idx0 + 4] = *(unsigned*)&h23;
    lo[row * 16 + idx0]     = *(unsigned*)&l01;
    lo[row * 16 + idx0 + 4] = *(unsigned*)&l23;
}

template<int TBM, int TBN, bool APACK, int EPI>
__device__ __forceinline__ void gemm_core(
    const float* __restrict__ A,
    const unsigned* __restrict__ Ahw, const unsigned* __restrict__ Alw,
    const unsigned* __restrict__ Bhw, const unsigned* __restrict__ Blw,
    int M, int N, int K, int bm, int bn,
    float* __restrict__ C1, int n1, const float* __restrict__ b1,
    float* __restrict__ C2, const float* __restrict__ b2,
    unsigned* __restrict__ Oh, unsigned* __restrict__ Ol) {

    __shared__ unsigned Ahi[TBM * 16], Alo[TBM * 16];
    __shared__ unsigned Bhi[TBN * 16], Blo[TBN * 16];

    constexpr int WMS = TBM / 32;                 // m-warps
    constexpr int API = APACK ? (TBM * 4) / 256 : 1;   // A packed uint4/thread
    constexpr int AFI = APACK ? 1 : (TBM * 8) / 256;   // A fp32 float4/thread
    constexpr int BPI = (TBN * 4) / 256;               // B packed uint4/thread

    const int tid = threadIdx.x;
    const int wid = tid >> 5;
    const int lane = tid & 31;
    const int wm = wid % WMS;
    const int wn = wid / WMS;
    const int g = lane >> 2;
    const int t = lane & 3;
    const int wpr = K >> 1;                       // packed words per row

    float acc[2][4][4];
    #pragma unroll
    for (int i = 0; i < 2; i++)
        #pragma unroll
        for (int j = 0; j < 4; j++)
            #pragma unroll
            for (int q = 0; q < 4; q++) acc[i][j][q] = 0.0f;

    const float4 z4 = make_float4(0.f, 0.f, 0.f, 0.f);
    const uint4 zu4 = make_uint4(0, 0, 0, 0);
    uint4 pah[API], pal[API];
    float4 saf[AFI];
    uint4 pbh[BPI], pbl[BPI];

    // ---- prefetch k-tile 0 ----
    if (APACK) {
        #pragma unroll
        for (int i = 0; i < API; i++) {
            int j = tid + i * 256; int row = j >> 2, q = j & 3;
            if (bm + row < M) {
                size_t gw = (size_t)(bm + row) * wpr + q * 4;
                pah[i] = *(const uint4*)&Ahw[gw];
                pal[i] = *(const uint4*)&Alw[gw];
            } else { pah[i] = zu4; pal[i] = zu4; }
        }
    } else {
        #pragma unroll
        for (int i = 0; i < AFI; i++) {
            int j = tid + i * 256; int row = j >> 3, lc = j & 7;
            saf[i] = (bm + row < M) ? *(const float4*)(A + (size_t)(bm + row) * K + lc * 4) : z4;
        }
    }
    #pragma unroll
    for (int i = 0; i < BPI; i++) {
        int j = tid + i * 256; int row = j >> 2, q = j & 3;
        if (bn + row < N) {
            size_t gw = (size_t)(bn + row) * wpr + q * 4;
            pbh[i] = *(const uint4*)&Bhw[gw];
            pbl[i] = *(const uint4*)&Blw[gw];
        } else { pbh[i] = zu4; pbl[i] = zu4; }
    }

    for (int k0 = 0; k0 < K; k0 += 32) {
        // ---- smem fill ----
        if (APACK) {
            #pragma unroll
            for (int i = 0; i < API; i++) {
                int j = tid + i * 256; int row = j >> 2, q = j & 3;
                *(uint4*)&Ahi[row * 16 + q * 4] = pah[i];
                *(uint4*)&Alo[row * 16 + q * 4] = pal[i];
            }
        } else {
            #pragma unroll
            for (int i = 0; i < AFI; i++) {
                int j = tid + i * 256;
                split_store(Ahi, Alo, j >> 3, j & 7, saf[i]);
            }
        }
        #pragma unroll
        for (int i = 0; i < BPI; i++) {
            int j = tid + i * 256; int row = j >> 2, q = j & 3;
            *(uint4*)&Bhi[row * 16 + q * 4] = pbh[i];
            *(uint4*)&Blo[row * 16 + q * 4] = pbl[i];
        }
        __syncthreads();

        // ---- prefetch next k-tile ----
        if (k0 + 32 < K) {
            int kt = ((k0 + 32) >> 5) << 4;
            if (APACK) {
                #pragma unroll
                for (int i = 0; i < API; i++) {
                    int j = tid + i * 256; int row = j >> 2, q = j & 3;
                    if (bm + row < M) {
                        size_t gw = (size_t)(bm + row) * wpr + kt + q * 4;
                        pah[i] = *(const uint4*)&Ahw[gw];
                        pal[i] = *(const uint4*)&Alw[gw];
                    } else { pah[i] = zu4; pal[i] = zu4; }
                }
            } else {
                #pragma unroll
                for (int i = 0; i < AFI; i++) {
                    int j = tid + i * 256; int row = j >> 3, lc = j & 7;
                    saf[i] = (bm + row < M) ?
                        *(const float4*)(A + (size_t)(bm + row) * K + k0 + 32 + lc * 4) : z4;
                }
            }
            #pragma unroll
            for (int i = 0; i < BPI; i++) {
                int j = tid + i * 256; int row = j >> 2, q = j & 3;
                if (bn + row < N) {
                    size_t gw = (size_t)(bn + row) * wpr + kt + q * 4;
                    pbh[i] = *(const uint4*)&Bhw[gw];
                    pbl[i] = *(const uint4*)&Blw[gw];
                } else { pbh[i] = zu4; pbl[i] = zu4; }
            }
        }

        // ---- fragments + MMA ----
        uint4 bh[4], bl[4];
        #pragma unroll
        for (int nt = 0; nt < 4; nt++) {
            int cn = wn * 32 + nt * 8 + g;
            bh[nt] = *(const uint4*)&Bhi[cn * 16 + t * 4];
            bl[nt] = *(const uint4*)&Blo[cn * 16 + t * 4];
        }
        #pragma unroll
        for (int mt = 0; mt < 2; mt++) {
            int r = wm * 32 + mt * 16 + g;
            uint4 ah0 = *(const uint4*)&Ahi[r * 16 + t * 4];
            uint4 ah1 = *(const uint4*)&Ahi[(r + 8) * 16 + t * 4];
            uint4 al0 = *(const uint4*)&Alo[r * 16 + t * 4];
            uint4 al1 = *(const uint4*)&Alo[(r + 8) * 16 + t * 4];
            #pragma unroll
            for (int nt = 0; nt < 4; nt++)
                mma_x3(acc[mt][nt], ah0, ah1, al0, al1, bh[nt], bl[nt]);
        }
        __syncthreads();
    }

    // ---- epilogue: c0=C[g][2t], c1=C[g][2t+1], c2=C[g+8][2t], c3=C[g+8][2t+1]
    const int n2w = N - n1;
    #pragma unroll
    for (int mt = 0; mt < 2; mt++) {
        #pragma unroll
        for (int nt = 0; nt < 4; nt++) {
            int col = bn + wn * 32 + nt * 8 + 2 * t;
            if (col >= N) continue;
            #pragma unroll
            for (int half = 0; half < 2; half++) {
                int row = bm + wm * 32 + mt * 16 + g + half * 8;
                if (row >= M) continue;
                float v0 = acc[mt][nt][half * 2 + 0];
                float v1 = acc[mt][nt][half * 2 + 1];
                if (EPI == 1) {
                    v0 += b1[col]; v1 += b1[col + 1];
                    __half h0 = __float2half_rn(v0), h1 = __float2half_rn(v1);
                    __half l0 = __float2half_rn(v0 - __half2float(h0));
                    __half l1 = __float2half_rn(v1 - __half2float(h1));
                    __half2 hh = __halves2half2(h0, h1);
                    __half2 ll = __halves2half2(l0, l1);
                    int widx = row * (N >> 1) + ((col >> 5) << 4) + permw(col & 31);
                    Oh[widx] = *(unsigned*)&hh;
                    Ol[widx] = *(unsigned*)&ll;
                } else {
                    if (col < n1) {
                        if (b1) { v0 += b1[col]; v1 += b1[col + 1]; }
                        *(float2*)(C1 + (size_t)row * n1 + col) = make_float2(v0, v1);
                    } else {
                        int cc = col - n1;
                        if (b2) { v0 += b2[cc]; v1 += b2[cc + 1]; }
                        *(float2*)(C2 + (size_t)row * n2w + cc) = make_float2(v0, v1);
                    }
                }
            }
        }
    }
}

// Fused input projections: A fp32, B packed, packed output into g_xb.
// grid.y tiles of 64 rows across the three segments.
__global__ __launch_bounds__(256, 2)
void gemm3_proj(const float* __restrict__ x0, const float* __restrict__ bb0,
                const float* __restrict__ x1, const float* __restrict__ bb1,
                const float* __restrict__ x2, const float* __restrict__ bb2,
                int T0, int T01) {
    int tile = blockIdx.y;
    const float* A; const float* bias;
    const unsigned *bh, *bl;
    int M, K, rowbase, ltile;
    if (tile < T0)       { A = x0; bias = bb0; bh = g_w0h; bl = g_w0l; M = N0; K = 256; rowbase = 0;       ltile = tile; }
    else if (tile < T01) { A = x1; bias = bb1; bh = g_w1h; bl = g_w1l; M = N1; K = 512; rowbase = N0;      ltile = tile - T0; }
    else                 { A = x2; bias = bb2; bh = g_w2h; bl = g_w2l; M = N2; K = 128; rowbase = N0 + N1; ltile = tile - T01; }
    gemm_core<64, 128, false, 1>(A, nullptr, nullptr, bh, bl,
        M, 128, K, ltile * 64, 0,
        nullptr, 128, bias, nullptr, nullptr,
        g_xbh + (size_t)rowbase * 64, g_xbl + (size_t)rowbase * 64);
}

// Layer 1: A packed (xb), B packed (W1), fp32 split outputs xt1/agg1.
__global__ __launch_bounds__(256, 2)
void gemm_l1(const float* __restrict__ bias1) {
    gemm_core<128, 64, true, 0>(nullptr, g_xbh, g_xbl, g_W1h, g_W1l,
        NTOT, 448, 128, blockIdx.y * 128, blockIdx.x * 64,
        g_xt1, 384, nullptr, g_agg1, bias1, nullptr, nullptr);
}

// Layer 2: A fp32 (agg1), B packed (W2), fp32 split outputs xt2/agg2.
__global__ __launch_bounds__(256, 2)
void gemm_l2(const float* __restrict__ bias2) {
    gemm_core<128, 64, false, 0>(g_agg1, nullptr, nullptr, g_W2h, g_W2l,
        NTOT, 112, 64, blockIdx.y * 128, blockIdx.x * 64,
        g_xt2, 96, nullptr, g_agg2, bias2, nullptr, nullptr);
}

// ---------------------------------------------------------------------------
// Edge scatter kernels: agg[dst] += inv[type,dst] * xt[src, type*dout .. ]
// ---------------------------------------------------------------------------
__device__ __forceinline__ void red_add_v4(float* addr, float4 v) {
    asm volatile("red.global.add.v4.f32 [%0], {%1, %2, %3, %4};"
                 :: "l"(addr), "f"(v.x), "f"(v.y), "f"(v.z), "f"(v.w)
                 : "memory");
}

__global__ __launch_bounds__(256)
void edge_scatter_64(const int* __restrict__ ei, const int* __restrict__ et) {
    int tglob = blockIdx.x * blockDim.x + threadIdx.x;
    int e = tglob >> 4;
    if (e >= NE) return;
    int lane = tglob & 15;
    int s = ei[e];
    int d = ei[NE + e];
    int r = et[e];
    float w = g_inv[r * NTOT + d];
    float4 v = *(const float4*)(g_xt1 + (size_t)s * 384 + r * 64 + lane * 4);
    red_add_v4(g_agg1 + (size_t)d * 64 + lane * 4,
               make_float4(v.x * w, v.y * w, v.z * w, v.w * w));
}

__global__ __launch_bounds__(256)
void edge_scatter_16(const int* __restrict__ ei, const int* __restrict__ et) {
    int tglob = blockIdx.x * blockDim.x + threadIdx.x;
    int e = tglob >> 2;
    if (e >= NE) return;
    int lane = tglob & 3;
    int s = ei[e];
    int d = ei[NE + e];
    int r = et[e];
    float w = g_inv[r * NTOT + d];
    float4 v = *(const float4*)(g_xt2 + (size_t)s * 96 + r * 16 + lane * 4);
    red_add_v4(g_agg2 + (size_t)d * 16 + lane * 4,
               make_float4(v.x * w, v.y * w, v.z * w, v.w * w));
}

// ---------------------------------------------------------------------------
// Softmax over the first N0 rows (16 cols each)
// ---------------------------------------------------------------------------
__global__ void softmax_kernel(float* __restrict__ out) {
    int row = blockIdx.x * blockDim.x + threadIdx.x;
    if (row >= N0) return;
    const float* p = g_agg2 + (size_t)row * 16;
    float v[16];
    #pragma unroll
    for (int i = 0; i < 4; i++) {
        float4 q = *(const float4*)(p + i * 4);
        v[i * 4 + 0] = q.x; v[i * 4 + 1] = q.y; v[i * 4 + 2] = q.z; v[i * 4 + 3] = q.w;
    }
    float mx = v[0];
    #pragma unroll
    for (int i = 1; i < 16; i++) mx = fmaxf(mx, v[i]);
    float s = 0.0f;
    #pragma unroll
    for (int i = 0; i < 16; i++) { v[i] = expf(v[i] - mx); s += v[i]; }
    float inv = 1.0f / s;
    float* o = out + (size_t)row * 16;
    #pragma unroll
    for (int i = 0; i < 4; i++) {
        float4 q = make_float4(v[i * 4 + 0] * inv, v[i * 4 + 1] * inv,
                               v[i * 4 + 2] * inv, v[i * 4 + 3] * inv);
        *(float4*)(o + i * 4) = q;
    }
}

// ---------------------------------------------------------------------------
// Launcher
// ---------------------------------------------------------------------------
extern "C" void kernel_launch(void* const* d_in, const int* in_sizes, int n_in,
                              void* d_out, int out_size) {
    (void)in_sizes; (void)n_in; (void)out_size;
    const float* x0     = (const float*)d_in[0];
    const float* x1     = (const float*)d_in[1];
    const float* x2     = (const float*)d_in[2];
    const float* lin_w0 = (const float*)d_in[3];
    const float* lin_b0 = (const float*)d_in[4];
    const float* lin_w1 = (const float*)d_in[5];
    const float* lin_b1 = (const float*)d_in[6];
    const float* lin_w2 = (const float*)d_in[7];
    const float* lin_b2 = (const float*)d_in[8];
    const float* bases1 = (const float*)d_in[9];
    const float* comp1  = (const float*)d_in[10];
    const float* root1  = (const float*)d_in[11];
    const float* bias1  = (const float*)d_in[12];
    const float* bases2 = (const float*)d_in[13];
    const float* comp2  = (const float*)d_in[14];
    const float* root2  = (const float*)d_in[15];
    const float* bias2  = (const float*)d_in[16];
    const int*   eidx   = (const int*)d_in[17];
    const int*   etyp   = (const int*)d_in[18];
    float* out = (float*)d_out;

    float *W1f, *W2f;
    unsigned *w0h, *w0l, *w1h, *w1l, *w2h, *w2l, *W1h, *W1l, *W2h, *W2l;
    cudaGetSymbolAddress((void**)&W1f, g_W1);
    cudaGetSymbolAddress((void**)&W2f, g_W2);
    cudaGetSymbolAddress((void**)&w0h, g_w0h); cudaGetSymbolAddress((void**)&w0l, g_w0l);
    cudaGetSymbolAddress((void**)&w1h, g_w1h); cudaGetSymbolAddress((void**)&w1l, g_w1l);
    cudaGetSymbolAddress((void**)&w2h, g_w2h); cudaGetSymbolAddress((void**)&w2l, g_w2l);
    cudaGetSymbolAddress((void**)&W1h, g_W1h); cudaGetSymbolAddress((void**)&W1l, g_W1l);
    cudaGetSymbolAddress((void**)&W2h, g_W2h); cudaGetSymbolAddress((void**)&W2l, g_W2l);

    // counts (shared by both layers)
    zero_cnt_kernel<<<(RN + 255) / 256, 256>>>();
    count_kernel<<<(NE + 255) / 256, 256>>>(eidx + NE, etyp);
    inv_kernel<<<(RN + 255) / 256, 256>>>();

    // pre-split weights into packed hi/lo fragment layout
    splitpack<<<(128 * 128 + 255) / 256, 256>>>(lin_w0, w0h, w0l, 128, 256);
    splitpack<<<(128 * 256 + 255) / 256, 256>>>(lin_w1, w1h, w1l, 128, 512);
    splitpack<<<(128 * 64  + 255) / 256, 256>>>(lin_w2, w2h, w2l, 128, 128);
    build_w1<<<(448 * 128 + 255) / 256, 256>>>(comp1, bases1, root1);
    splitpack<<<(448 * 64 + 255) / 256, 256>>>(W1f, W1h, W1l, 448, 128);
    build_w2<<<(112 * 64 + 255) / 256, 256>>>(comp2, bases2, root2);
    splitpack<<<(112 * 32 + 255) / 256, 256>>>(W2f, W2h, W2l, 112, 64);

    // typed input projections -> packed xb (fused single launch)
    const int T0 = (N0 + 63) / 64;     // 469
    const int T1 = (N1 + 63) / 64;     // 782
    const int T2 = (N2 + 63) / 64;     // 313
    gemm3_proj<<<dim3(1, T0 + T1 + T2), 256>>>(x0, lin_b0, x1, lin_b1, x2, lin_b2,
                                               T0, T0 + T1);

    // layer 1: xt1 (relation cols) + agg1 init (root+bias cols)
    gemm_l1<<<dim3(7, (NTOT + 127) / 128), 256>>>(bias1);
    edge_scatter_64<<<(NE * 16) / 256, 256>>>(eidx, etyp);

    // layer 2: xt2 + agg2 init
    gemm_l2<<<dim3(2, (NTOT + 127) / 128), 256>>>(bias2);
    edge_scatter_16<<<(NE * 4) / 256, 256>>>(eidx, etyp);

    // softmax over author rows
    softmax_kernel<<<(N0 + 255) / 256, 256>>>(out);
}

// round 10
// speedup vs baseline: 1.0145x; 1.0145x over previous
#include <cuda_runtime.h>
#include <cuda_fp16.h>
#include <cstdint>
#include <math.h>

// Problem constants (fixed by the dataset)
#define N0 30000
#define N1 50000
#define N2 20000
#define NTOT 100000
#define NE 1600000
#define NR 6
#define RN (NR * NTOT)

// ---------------------------------------------------------------------------
// Scratch (static __device__ globals; allocation-free per harness rules)
// ---------------------------------------------------------------------------
__device__ unsigned g_xbh[(size_t)NTOT * 64];   // packed hi: proj output (K=128)
__device__ unsigned g_xbl[(size_t)NTOT * 64];   // packed lo
__device__ unsigned g_xt1h[(size_t)NTOT * 192]; // layer1 transform, fp16 half2 [N][384]
__device__ float    g_agg1[(size_t)NTOT * 64];  // layer1 accumulator / h1 (fp32)
__device__ unsigned g_xt2h[(size_t)NTOT * 48];  // layer2 transform, fp16 half2 [N][96]
__device__ float    g_agg2[(size_t)NTOT * 16];  // layer2 accumulator / h2 (fp32)
__device__ int   g_cnt[RN];
__device__ float g_inv[RN];
__device__ float g_W1[448 * 128];               // fp32 [n][k] (intermediate)
__device__ float g_W2[112 * 64];
// packed weights (hi/lo half2 words, permuted fragment layout)
__device__ unsigned g_w0h[128 * 128], g_w0l[128 * 128];   // lin_w0: 128x256
__device__ unsigned g_w1h[128 * 256], g_w1l[128 * 256];   // lin_w1: 128x512
__device__ unsigned g_w2h[128 * 64],  g_w2l[128 * 64];    // lin_w2: 128x128
__device__ unsigned g_W1h[448 * 64],  g_W1l[448 * 64];    // W1: 448x128
__device__ unsigned g_W2h[112 * 32],  g_W2l[112 * 32];    // W2: 112x64

// permuted half2-word index within a 32-col k-tile (kk even, in [0,32))
__device__ __forceinline__ int permw(int kk) {
    int c = kk >> 2;
    int idx0 = 8 * (c & 1) + 2 * (c >> 2) + ((c >> 1) & 1);
    return idx0 + ((kk >> 1) & 1) * 4;
}

// ---------------------------------------------------------------------------
// Small helper kernels
// ---------------------------------------------------------------------------
__global__ void zero_cnt_kernel() {
    int i = blockIdx.x * blockDim.x + threadIdx.x;
    if (i < RN) g_cnt[i] = 0;
}

__global__ void count_kernel(const int* __restrict__ dst, const int* __restrict__ et) {
    int e = blockIdx.x * blockDim.x + threadIdx.x;
    if (e < NE) atomicAdd(&g_cnt[et[e] * NTOT + dst[e]], 1);
}

__global__ void inv_kernel() {
    int i = blockIdx.x * blockDim.x + threadIdx.x;
    if (i < RN) {
        int c = g_cnt[i];
        g_inv[i] = 1.0f / (float)(c > 1 ? c : 1);
    }
}

__global__ void build_w1(const float* __restrict__ comp1, const float* __restrict__ bases1,
                         const float* __restrict__ root1) {
    int idx = blockIdx.x * blockDim.x + threadIdx.x;
    if (idx >= 448 * 128) return;
    int n = idx >> 7, k = idx & 127;
    float v;
    if (n < 384) {
        int r = n >> 6, o = n & 63;
        v = 0.0f;
        for (int b = 0; b < 30; b++)
            v += comp1[r * 30 + b] * bases1[((size_t)b * 128 + k) * 64 + o];
    } else {
        v = root1[k * 64 + (n - 384)];
    }
    g_W1[idx] = v;
}

__global__ void build_w2(const float* __restrict__ comp2, const float* __restrict__ bases2,
                         const float* __restrict__ root2) {
    int idx = blockIdx.x * blockDim.x + threadIdx.x;
    if (idx >= 112 * 64) return;
    int n = idx >> 6, k = idx & 63;
    float v;
    if (n < 96) {
        int r = n >> 4, o = n & 15;
        v = 0.0f;
        for (int b = 0; b < 30; b++)
            v += comp2[r * 30 + b] * bases2[((size_t)b * 64 + k) * 16 + o];
    } else {
        v = root2[k * 16 + (n - 96)];
    }
    g_W2[idx] = v;
}

// fp32 [Nrows][K] -> packed hi/lo half2 words in permuted fragment layout
__global__ void splitpack(const float* __restrict__ src, unsigned* __restrict__ hi,
                          unsigned* __restrict__ lo, int Nrows, int K) {
    int w = blockIdx.x * blockDim.x + threadIdx.x;
    int wpr = K >> 1;
    if (w >= Nrows * wpr) return;
    int row = w / wpr, kp = w - row * wpr;
    int k = kp * 2;
    float v0 = src[(size_t)row * K + k];
    float v1 = src[(size_t)row * K + k + 1];
    __half h0 = __float2half_rn(v0), h1 = __float2half_rn(v1);
    __half l0 = __float2half_rn(v0 - __half2float(h0));
    __half l1 = __float2half_rn(v1 - __half2float(h1));
    __half2 hh = __halves2half2(h0, h1);
    __half2 ll = __halves2half2(l0, l1);
    int widx = row * wpr + ((k >> 5) << 4) + permw(k & 31);
    hi[widx] = *(unsigned*)&hh;
    lo[widx] = *(unsigned*)&ll;
}

// ---------------------------------------------------------------------------
// FP16x3 split-precision tensor-core GEMM core (templated).
//   C[m,n] = sum_k A[m,k]*Bw[n,k]; a*b ~= ahi*bhi + ahi*blo + alo*bhi.
// 256 threads = 8 warps, 32x32 warptile: (TBM/32) m-warps x (TBN/32) n-warps.
// B always pre-packed; A either fp32 (on-the-fly split) or pre-packed.
// EPI: 1 = packed hi/lo output (+bias b1, proj)
//      2 = cols<n1 -> half2 output Oh; cols>=n1 -> fp32 C2 (+bias b2)
// ---------------------------------------------------------------------------
__device__ __forceinline__ void mma_fp16(float* c, unsigned a0, unsigned a1,
                                         unsigned a2, unsigned a3,
                                         unsigned b0, unsigned b1) {
    asm volatile(
        "mma.sync.aligned.m16n8k16.row.col.f32.f16.f16.f32 "
        "{%0,%1,%2,%3}, {%4,%5,%6,%7}, {%8,%9}, {%0,%1,%2,%3};"
        : "+f"(c[0]), "+f"(c[1]), "+f"(c[2]), "+f"(c[3])
        : "r"(a0), "r"(a1), "r"(a2), "r"(a3), "r"(b0), "r"(b1));
}

__device__ __forceinline__ void mma_x3(float* c,
                                       const uint4& ah0, const uint4& ah1,
                                       const uint4& al0, const uint4& al1,
                                       const uint4& bh,  const uint4& bl) {
    mma_fp16(c, ah0.x, ah1.x, ah0.y, ah1.y, bh.x, bh.y);
    mma_fp16(c, ah0.x, ah1.x, ah0.y, ah1.y, bl.x, bl.y);
    mma_fp16(c, al0.x, al1.x, al0.y, al1.y, bh.x, bh.y);
    mma_fp16(c, ah0.z, ah1.z, ah0.w, ah1.w, bh.z, bh.w);
    mma_fp16(c, ah0.z, ah1.z, ah0.w, ah1.w, bl.z, bl.w);
    mma_fp16(c, al0.z, al1.z, al0.w, al1.w, bh.z, bh.w);
}

__device__ __forceinline__ void split_store(unsigned* hi, unsigned* lo,
                                            int row, int c, float4 v) {
    __half hx0 = __float2half_rn(v.x);
    __half hx1 = __float2half_rn(v.y);
    __half hx2 = __float2half_rn(v.z);
    __half hx3 = __float2half_rn(v.w);
    __half lx0 = __float2half_rn(v.x - __half2float(hx0));
    __half lx1 = __float2half_rn(v.y - __half2float(hx1));
    __half lx2 = __float2half_rn(v.z - __half2float(hx2));
    __half lx3 = __float2half_rn(v.w - __half2float(hx3));
    int idx0 = 8 * (c & 1) + 2 * (c >> 2) + ((c >> 1) & 1);
    __half2 h01 = __halves2half2(hx0, hx1);
    __half2 h23 = __halves2half2(hx2, hx3);
    __half2 l01 = __halves2half2(lx0, lx1);
    __half2 l23 = __halves2half2(lx2, lx3);
    hi[row * 16 + idx0]     = *(unsigned*)&h01;
    hi[row * 16 + idx0 + 4] = *(unsigned*)&h23;
    lo[row * 16 + idx0]     = *(unsigned*)&l01;
    lo[row * 16 + idx0 + 4] = *(unsigned*)&l23;
}

template<int TBM, int TBN, bool APACK, int EPI>
__device__ __forceinline__ void gemm_core(
    const float* __restrict__ A,
    const unsigned* __restrict__ Ahw, const unsigned* __restrict__ Alw,
    const unsigned* __restrict__ Bhw, const unsigned* __restrict__ Blw,
    int M, int N, int K, int bm, int bn,
    int n1, const float* __restrict__ b1,
    float* __restrict__ C2, const float* __restrict__ b2,
    unsigned* __restrict__ Oh, unsigned* __restrict__ Ol) {

    __shared__ unsigned Ahi[TBM * 16], Alo[TBM * 16];
    __shared__ unsigned Bhi[TBN * 16], Blo[TBN * 16];

    constexpr int WMS = TBM / 32;
    constexpr int API = APACK ? (TBM * 4) / 256 : 1;
    constexpr int AFI = APACK ? 1 : (TBM * 8) / 256;
    constexpr int BPI = (TBN * 4) / 256;

    const int tid = threadIdx.x;
    const int wid = tid >> 5;
    const int lane = tid & 31;
    const int wm = wid % WMS;
    const int wn = wid / WMS;
    const int g = lane >> 2;
    const int t = lane & 3;
    const int wpr = K >> 1;

    float acc[2][4][4];
    #pragma unroll
    for (int i = 0; i < 2; i++)
        #pragma unroll
        for (int j = 0; j < 4; j++)
            #pragma unroll
            for (int q = 0; q < 4; q++) acc[i][j][q] = 0.0f;

    const float4 z4 = make_float4(0.f, 0.f, 0.f, 0.f);
    const uint4 zu4 = make_uint4(0, 0, 0, 0);
    uint4 pah[API], pal[API];
    float4 saf[AFI];
    uint4 pbh[BPI], pbl[BPI];

    // ---- prefetch k-tile 0 ----
    if (APACK) {
        #pragma unroll
        for (int i = 0; i < API; i++) {
            int j = tid + i * 256; int row = j >> 2, q = j & 3;
            if (bm + row < M) {
                size_t gw = (size_t)(bm + row) * wpr + q * 4;
                pah[i] = *(const uint4*)&Ahw[gw];
                pal[i] = *(const uint4*)&Alw[gw];
            } else { pah[i] = zu4; pal[i] = zu4; }
        }
    } else {
        #pragma unroll
        for (int i = 0; i < AFI; i++) {
            int j = tid + i * 256; int row = j >> 3, lc = j & 7;
            saf[i] = (bm + row < M) ? *(const float4*)(A + (size_t)(bm + row) * K + lc * 4) : z4;
        }
    }
    #pragma unroll
    for (int i = 0; i < BPI; i++) {
        int j = tid + i * 256; int row = j >> 2, q = j & 3;
        if (bn + row < N) {
            size_t gw = (size_t)(bn + row) * wpr + q * 4;
            pbh[i] = *(const uint4*)&Bhw[gw];
            pbl[i] = *(const uint4*)&Blw[gw];
        } else { pbh[i] = zu4; pbl[i] = zu4; }
    }

    for (int k0 = 0; k0 < K; k0 += 32) {
        if (APACK) {
            #pragma unroll
            for (int i = 0; i < API; i++) {
                int j = tid + i * 256; int row = j >> 2, q = j & 3;
                *(uint4*)&Ahi[row * 16 + q * 4] = pah[i];
                *(uint4*)&Alo[row * 16 + q * 4] = pal[i];
            }
        } else {
            #pragma unroll
            for (int i = 0; i < AFI; i++) {
                int j = tid + i * 256;
                split_store(Ahi, Alo, j >> 3, j & 7, saf[i]);
            }
        }
        #pragma unroll
        for (int i = 0; i < BPI; i++) {
            int j = tid + i * 256; int row = j >> 2, q = j & 3;
            *(uint4*)&Bhi[row * 16 + q * 4] = pbh[i];
            *(uint4*)&Blo[row * 16 + q * 4] = pbl[i];
        }
        __syncthreads();

        if (k0 + 32 < K) {
            int kt = ((k0 + 32) >> 5) << 4;
            if (APACK) {
                #pragma unroll
                for (int i = 0; i < API; i++) {
                    int j = tid + i * 256; int row = j >> 2, q = j & 3;
                    if (bm + row < M) {
                        size_t gw = (size_t)(bm + row) * wpr + kt + q * 4;
                        pah[i] = *(const uint4*)&Ahw[gw];
                        pal[i] = *(const uint4*)&Alw[gw];
                    } else { pah[i] = zu4; pal[i] = zu4; }
                }
            } else {
                #pragma unroll
                for (int i = 0; i < AFI; i++) {
                    int j = tid + i * 256; int row = j >> 3, lc = j & 7;
                    saf[i] = (bm + row < M) ?
                        *(const float4*)(A + (size_t)(bm + row) * K + k0 + 32 + lc * 4) : z4;
                }
            }
            #pragma unroll
            for (int i = 0; i < BPI; i++) {
                int j = tid + i * 256; int row = j >> 2, q = j & 3;
                if (bn + row < N) {
                    size_t gw = (size_t)(bn + row) * wpr + kt + q * 4;
                    pbh[i] = *(const uint4*)&Bhw[gw];
                    pbl[i] = *(const uint4*)&Blw[gw];
                } else { pbh[i] = zu4; pbl[i] = zu4; }
            }
        }

        uint4 bh[4], bl[4];
        #pragma unroll
        for (int nt = 0; nt < 4; nt++) {
            int cn = wn * 32 + nt * 8 + g;
            bh[nt] = *(const uint4*)&Bhi[cn * 16 + t * 4];
            bl[nt] = *(const uint4*)&Blo[cn * 16 + t * 4];
        }
        #pragma unroll
        for (int mt = 0; mt < 2; mt++) {
            int r = wm * 32 + mt * 16 + g;
            uint4 ah0 = *(const uint4*)&Ahi[r * 16 + t * 4];
            uint4 ah1 = *(const uint4*)&Ahi[(r + 8) * 16 + t * 4];
            uint4 al0 = *(const uint4*)&Alo[r * 16 + t * 4];
            uint4 al1 = *(const uint4*)&Alo[(r + 8) * 16 + t * 4];
            #pragma unroll
            for (int nt = 0; nt < 4; nt++)
                mma_x3(acc[mt][nt], ah0, ah1, al0, al1, bh[nt], bl[nt]);
        }
        __syncthreads();
    }

    // ---- epilogue: c0=C[g][2t], c1=C[g][2t+1], c2=C[g+8][2t], c3=C[g+8][2t+1]
    const int n2w = N - n1;
    #pragma unroll
    for (int mt = 0; mt < 2; mt++) {
        #pragma unroll
        for (int nt = 0; nt < 4; nt++) {
            int col = bn + wn * 32 + nt * 8 + 2 * t;
            if (col >= N) continue;
            #pragma unroll
            for (int half = 0; half < 2; half++) {
                int row = bm + wm * 32 + mt * 16 + g + half * 8;
                if (row >= M) continue;
                float v0 = acc[mt][nt][half * 2 + 0];
                float v1 = acc[mt][nt][half * 2 + 1];
                if (EPI == 1) {
                    v0 += b1[col]; v1 += b1[col + 1];
                    __half h0 = __float2half_rn(v0), h1 = __float2half_rn(v1);
                    __half l0 = __float2half_rn(v0 - __half2float(h0));
                    __half l1 = __float2half_rn(v1 - __half2float(h1));
                    __half2 hh = __halves2half2(h0, h1);
                    __half2 ll = __halves2half2(l0, l1);
                    int widx = row * (N >> 1) + ((col >> 5) << 4) + permw(col & 31);
                    Oh[widx] = *(unsigned*)&hh;
                    Ol[widx] = *(unsigned*)&ll;
                } else { // EPI == 2
                    if (col < n1) {
                        __half2 hv = __halves2half2(__float2half_rn(v0), __float2half_rn(v1));
                        Oh[(size_t)row * (n1 >> 1) + (col >> 1)] = *(unsigned*)&hv;
                    } else {
                        int cc = col - n1;
                        v0 += b2[cc]; v1 += b2[cc + 1];
                        *(float2*)(C2 + (size_t)row * n2w + cc) = make_float2(v0, v1);
                    }
                }
            }
        }
    }
}

// Fused input projections: A fp32, B packed, packed hi/lo output into g_xb.
__global__ __launch_bounds__(256, 2)
void gemm3_proj(const float* __restrict__ x0, const float* __restrict__ bb0,
                const float* __restrict__ x1, const float* __restrict__ bb1,
                const float* __restrict__ x2, const float* __restrict__ bb2,
                int T0, int T01) {
    int tile = blockIdx.y;
    const float* A; const float* bias;
    const unsigned *bh, *bl;
    int M, K, rowbase, ltile;
    if (tile < T0)       { A = x0; bias = bb0; bh = g_w0h; bl = g_w0l; M = N0; K = 256; rowbase = 0;       ltile = tile; }
    else if (tile < T01) { A = x1; bias = bb1; bh = g_w1h; bl = g_w1l; M = N1; K = 512; rowbase = N0;      ltile = tile - T0; }
    else                 { A = x2; bias = bb2; bh = g_w2h; bl = g_w2l; M = N2; K = 128; rowbase = N0 + N1; ltile = tile - T01; }
    gemm_core<64, 128, false, 1>(A, nullptr, nullptr, bh, bl,
        M, 128, K, ltile * 64, 0,
        128, bias, nullptr, nullptr,
        g_xbh + (size_t)rowbase * 64, g_xbl + (size_t)rowbase * 64);
}

// Layer 1: A packed (xb), B packed (W1); xt1 -> fp16, agg1 -> fp32 (+bias).
__global__ __launch_bounds__(256, 2)
void gemm_l1(const float* __restrict__ bias1) {
    gemm_core<128, 64, true, 2>(nullptr, g_xbh, g_xbl, g_W1h, g_W1l,
        NTOT, 448, 128, blockIdx.y * 128, blockIdx.x * 64,
        384, nullptr, g_agg1, bias1, g_xt1h, nullptr);
}

// Layer 2: A fp32 (agg1), B packed (W2); xt2 -> fp16, agg2 -> fp32 (+bias).
__global__ __launch_bounds__(256, 2)
void gemm_l2(const float* __restrict__ bias2) {
    gemm_core<128, 64, false, 2>(g_agg1, nullptr, nullptr, g_W2h, g_W2l,
        NTOT, 112, 64, blockIdx.y * 128, blockIdx.x * 64,
        96, nullptr, g_agg2, bias2, g_xt2h, nullptr);
}

// ---------------------------------------------------------------------------
// Edge scatter: agg[dst] += inv[type,dst] * xt[src, type*dout ..] (fp16 gather)
// ---------------------------------------------------------------------------
__device__ __forceinline__ void red_add_v4(float* addr, float4 v) {
    asm volatile("red.global.add.v4.f32 [%0], {%1, %2, %3, %4};"
                 :: "l"(addr), "f"(v.x), "f"(v.y), "f"(v.z), "f"(v.w)
                 : "memory");
}

// Layer 1: dout=64, 8 lanes/edge, each gathers uint4 = 8 halves.
__global__ __launch_bounds__(256)
void edge_scatter_64(const int* __restrict__ ei, const int* __restrict__ et) {
    int tglob = blockIdx.x * blockDim.x + threadIdx.x;
    int e = tglob >> 3;
    if (e >= NE) return;
    int lane = tglob & 7;
    int s = ei[e];
    int d = ei[NE + e];
    int r = et[e];
    float w = g_inv[r * NTOT + d];
    uint4 pv = *(const uint4*)(g_xt1h + (size_t)s * 192 + r * 32 + lane * 4);
    float2 f0 = __half22float2(*(__half2*)&pv.x);
    float2 f1 = __half22float2(*(__half2*)&pv.y);
    float2 f2 = __half22float2(*(__half2*)&pv.z);
    float2 f3 = __half22float2(*(__half2*)&pv.w);
    float* dstp = g_agg1 + (size_t)d * 64 + lane * 8;
    red_add_v4(dstp,     make_float4(f0.x * w, f0.y * w, f1.x * w, f1.y * w));
    red_add_v4(dstp + 4, make_float4(f2.x * w, f2.y * w, f3.x * w, f3.y * w));
}

// Layer 2: dout=16, 2 lanes/edge, each gathers uint4 = 8 halves.
__global__ __launch_bounds__(256)
void edge_scatter_16(const int* __restrict__ ei, const int* __restrict__ et) {
    int tglob = blockIdx.x * blockDim.x + threadIdx.x;
    int e = tglob >> 1;
    if (e >= NE) return;
    int lane = tglob & 1;
    int s = ei[e];
    int d = ei[NE + e];
    int r = et[e];
    float w = g_inv[r * NTOT + d];
    uint4 pv = *(const uint4*)(g_xt2h + (size_t)s * 48 + r * 8 + lane * 4);
    float2 f0 = __half22float2(*(__half2*)&pv.x);
    float2 f1 = __half22float2(*(__half2*)&pv.y);
    float2 f2 = __half22float2(*(__half2*)&pv.z);
    float2 f3 = __half22float2(*(__half2*)&pv.w);
    float* dstp = g_agg2 + (size_t)d * 16 + lane * 8;
    red_add_v4(dstp,     make_float4(f0.x * w, f0.y * w, f1.x * w, f1.y * w));
    red_add_v4(dstp + 4, make_float4(f2.x * w, f2.y * w, f3.x * w, f3.y * w));
}

// ---------------------------------------------------------------------------
// Softmax over the first N0 rows (16 cols each)
// ---------------------------------------------------------------------------
__global__ void softmax_kernel(float* __restrict__ out) {
    int row = blockIdx.x * blockDim.x + threadIdx.x;
    if (row >= N0) return;
    const float* p = g_agg2 + (size_t)row * 16;
    float v[16];
    #pragma unroll
    for (int i = 0; i < 4; i++) {
        float4 q = *(const float4*)(p + i * 4);
        v[i * 4 + 0] = q.x; v[i * 4 + 1] = q.y; v[i * 4 + 2] = q.z; v[i * 4 + 3] = q.w;
    }
    float mx = v[0];
    #pragma unroll
    for (int i = 1; i < 16; i++) mx = fmaxf(mx, v[i]);
    float s = 0.0f;
    #pragma unroll
    for (int i = 0; i < 16; i++) { v[i] = expf(v[i] - mx); s += v[i]; }
    float inv = 1.0f / s;
    float* o = out + (size_t)row * 16;
    #pragma unroll
    for (int i = 0; i < 4; i++) {
        float4 q = make_float4(v[i * 4 + 0] * inv, v[i * 4 + 1] * inv,
                               v[i * 4 + 2] * inv, v[i * 4 + 3] * inv);
        *(float4*)(o + i * 4) = q;
    }
}

// ---------------------------------------------------------------------------
// Launcher
// ---------------------------------------------------------------------------
extern "C" void kernel_launch(void* const* d_in, const int* in_sizes, int n_in,
                              void* d_out, int out_size) {
    (void)in_sizes; (void)n_in; (void)out_size;
    const float* x0     = (const float*)d_in[0];
    const float* x1     = (const float*)d_in[1];
    const float* x2     = (const float*)d_in[2];
    const float* lin_w0 = (const float*)d_in[3];
    const float* lin_b0 = (const float*)d_in[4];
    const float* lin_w1 = (const float*)d_in[5];
    const float* lin_b1 = (const float*)d_in[6];
    const float* lin_w2 = (const float*)d_in[7];
    const float* lin_b2 = (const float*)d_in[8];
    const float* bases1 = (const float*)d_in[9];
    const float* comp1  = (const float*)d_in[10];
    const float* root1  = (const float*)d_in[11];
    const float* bias1  = (const float*)d_in[12];
    const float* bases2 = (const float*)d_in[13];
    const float* comp2  = (const float*)d_in[14];
    const float* root2  = (const float*)d_in[15];
    const float* bias2  = (const float*)d_in[16];
    const int*   eidx   = (const int*)d_in[17];
    const int*   etyp   = (const int*)d_in[18];
    float* out = (float*)d_out;

    float *W1f, *W2f;
    unsigned *w0h, *w0l, *w1h, *w1l, *w2h, *w2l, *W1h, *W1l, *W2h, *W2l;
    cudaGetSymbolAddress((void**)&W1f, g_W1);
    cudaGetSymbolAddress((void**)&W2f, g_W2);
    cudaGetSymbolAddress((void**)&w0h, g_w0h); cudaGetSymbolAddress((void**)&w0l, g_w0l);
    cudaGetSymbolAddress((void**)&w1h, g_w1h); cudaGetSymbolAddress((void**)&w1l, g_w1l);
    cudaGetSymbolAddress((void**)&w2h, g_w2h); cudaGetSymbolAddress((void**)&w2l, g_w2l);
    cudaGetSymbolAddress((void**)&W1h, g_W1h); cudaGetSymbolAddress((void**)&W1l, g_W1l);
    cudaGetSymbolAddress((void**)&W2h, g_W2h); cudaGetSymbolAddress((void**)&W2l, g_W2l);

    // counts (shared by both layers)
    zero_cnt_kernel<<<(RN + 255) / 256, 256>>>();
    count_kernel<<<(NE + 255) / 256, 256>>>(eidx + NE, etyp);
    inv_kernel<<<(RN + 255) / 256, 256>>>();

    // pre-split weights into packed hi/lo fragment layout
    splitpack<<<(128 * 128 + 255) / 256, 256>>>(lin_w0, w0h, w0l, 128, 256);
    splitpack<<<(128 * 256 + 255) / 256, 256>>>(lin_w1, w1h, w1l, 128, 512);
    splitpack<<<(128 * 64  + 255) / 256, 256>>>(lin_w2, w2h, w2l, 128, 128);
    build_w1<<<(448 * 128 + 255) / 256, 256>>>(comp1, bases1, root1);
    splitpack<<<(448 * 64 + 255) / 256, 256>>>(W1f, W1h, W1l, 448, 128);
    build_w2<<<(112 * 64 + 255) / 256, 256>>>(comp2, bases2, root2);
    splitpack<<<(112 * 32 + 255) / 256, 256>>>(W2f, W2h, W2l, 112, 64);

    // typed input projections -> packed xb (fused single launch)
    const int T0 = (N0 + 63) / 64;
    const int T1 = (N1 + 63) / 64;
    const int T2 = (N2 + 63) / 64;
    gemm3_proj<<<dim3(1, T0 + T1 + T2), 256>>>(x0, lin_b0, x1, lin_b1, x2, lin_b2,
                                               T0, T0 + T1);

    // layer 1: xt1 (fp16 relation cols) + agg1 init (root+bias cols)
    gemm_l1<<<dim3(7, (NTOT + 127) / 128), 256>>>(bias1);
    edge_scatter_64<<<(NE * 8) / 256, 256>>>(eidx, etyp);

    // layer 2: xt2 (fp16) + agg2 init
    gemm_l2<<<dim3(2, (NTOT + 127) / 128), 256>>>(bias2);
    edge_scatter_16<<<(NE * 2 + 255) / 256, 256>>>(eidx, etyp);

    // softmax over author rows
    softmax_kernel<<<(N0 + 255) / 256, 256>>>(out);
}

// round 11
// speedup vs baseline: 1.0337x; 1.0189x over previous
#include <cuda_runtime.h>
#include <cuda_fp16.h>
#include <cstdint>
#include <math.h>

// Problem constants (fixed by the dataset)
#define N0 30000
#define N1 50000
#define N2 20000
#define NTOT 100000
#define NE 1600000
#define NR 6
#define RN (NR * NTOT)

// ---------------------------------------------------------------------------
// Scratch (static __device__ globals; allocation-free per harness rules)
// ---------------------------------------------------------------------------
__device__ unsigned g_xbh[(size_t)NTOT * 64];   // packed hi: proj output (K=128)
__device__ unsigned g_xbl[(size_t)NTOT * 64];   // packed lo
__device__ unsigned g_xt1h[(size_t)NTOT * 192]; // layer1 transform, fp16 half2 [N][384]
__device__ float    g_agg1[(size_t)NTOT * 64];  // layer1 accumulator / h1 (fp32)
__device__ unsigned g_xt2h[(size_t)NTOT * 48];  // layer2 transform, fp16 half2 [N][96]
__device__ float    g_agg2[(size_t)NTOT * 16];  // layer2 accumulator / h2 (fp32)
__device__ int   g_cnt[RN];                     // per (r,dst) edge counts
__device__ int   g_off[RN];                     // segment base slot
__device__ int   g_cur[RN];                     // fill cursors
__device__ int   g_psrc[NE];                    // src node per slot (CSR payload)
__device__ int   g_total;                       // slot allocator
__device__ float g_W1[448 * 128];               // fp32 [n][k] (intermediate)
__device__ float g_W2[112 * 64];
// packed weights (hi/lo half2 words, permuted fragment layout)
__device__ unsigned g_w0h[128 * 128], g_w0l[128 * 128];   // lin_w0: 128x256
__device__ unsigned g_w1h[128 * 256], g_w1l[128 * 256];   // lin_w1: 128x512
__device__ unsigned g_w2h[128 * 64],  g_w2l[128 * 64];    // lin_w2: 128x128
__device__ unsigned g_W1h[448 * 64],  g_W1l[448 * 64];    // W1: 448x128
__device__ unsigned g_W2h[112 * 32],  g_W2l[112 * 32];    // W2: 112x64

// permuted half2-word index within a 32-col k-tile (kk even, in [0,32))
__device__ __forceinline__ int permw(int kk) {
    int c = kk >> 2;
    int idx0 = 8 * (c & 1) + 2 * (c >> 2) + ((c >> 1) & 1);
    return idx0 + ((kk >> 1) & 1) * 4;
}

// ---------------------------------------------------------------------------
// Graph preprocessing: counts -> segment offsets -> CSR fill
// ---------------------------------------------------------------------------
__global__ void zero_cnt_kernel() {
    int i = blockIdx.x * blockDim.x + threadIdx.x;
    if (i == 0) g_total = 0;
    if (i < RN) g_cnt[i] = 0;
}

__global__ void count_kernel(const int* __restrict__ dst, const int* __restrict__ et) {
    int e = blockIdx.x * blockDim.x + threadIdx.x;
    if (e < NE) atomicAdd(&g_cnt[et[e] * NTOT + dst[e]], 1);
}

// Block-aggregated slot allocation: exclusive prefix within block, one
// atomicAdd on g_total per 256 segments. Segment placement is
// nondeterministic across launches but segment sums are order-insensitive
// at the tolerance level (same as prior atomic design).
__global__ void alloc_kernel() {
    __shared__ int warp_sums[8];
    __shared__ int block_base;
    int i = blockIdx.x * 256 + threadIdx.x;
    int lane = threadIdx.x & 31, w = threadIdx.x >> 5;
    int c = (i < RN) ? g_cnt[i] : 0;
    int x = c;
    #pragma unroll
    for (int o = 1; o < 32; o <<= 1) {
        int y = __shfl_up_sync(0xffffffffu, x, o);
        if (lane >= o) x += y;
    }
    if (lane == 31) warp_sums[w] = x;
    __syncthreads();
    if (threadIdx.x < 8) {
        int v = warp_sums[threadIdx.x];
        #pragma unroll
        for (int o = 1; o < 8; o <<= 1) {
            int y = __shfl_up_sync(0xffu, v, o);
            if ((int)threadIdx.x >= o) v += y;
        }
        warp_sums[threadIdx.x] = v;
        if (threadIdx.x == 7) block_base = atomicAdd(&g_total, v);
    }
    __syncthreads();
    int base = block_base + (w ? warp_sums[w - 1] : 0) + x - c;
    if (i < RN) { g_off[i] = base; g_cur[i] = base; }
}

__global__ void fill_kernel(const int* __restrict__ ei, const int* __restrict__ et) {
    int e = blockIdx.x * blockDim.x + threadIdx.x;
    if (e >= NE) return;
    int s = ei[e];
    int d = ei[NE + e];
    int r = et[e];
    int pos = atomicAdd(&g_cur[r * NTOT + d], 1);
    g_psrc[pos] = s;
}

// ---------------------------------------------------------------------------
// Weight-building helpers
// ---------------------------------------------------------------------------
__global__ void build_w1(const float* __restrict__ comp1, const float* __restrict__ bases1,
                         const float* __restrict__ root1) {
    int idx = blockIdx.x * blockDim.x + threadIdx.x;
    if (idx >= 448 * 128) return;
    int n = idx >> 7, k = idx & 127;
    float v;
    if (n < 384) {
        int r = n >> 6, o = n & 63;
        v = 0.0f;
        for (int b = 0; b < 30; b++)
            v += comp1[r * 30 + b] * bases1[((size_t)b * 128 + k) * 64 + o];
    } else {
        v = root1[k * 64 + (n - 384)];
    }
    g_W1[idx] = v;
}

__global__ void build_w2(const float* __restrict__ comp2, const float* __restrict__ bases2,
                         const float* __restrict__ root2) {
    int idx = blockIdx.x * blockDim.x + threadIdx.x;
    if (idx >= 112 * 64) return;
    int n = idx >> 6, k = idx & 63;
    float v;
    if (n < 96) {
        int r = n >> 4, o = n & 15;
        v = 0.0f;
        for (int b = 0; b < 30; b++)
            v += comp2[r * 30 + b] * bases2[((size_t)b * 64 + k) * 16 + o];
    } else {
        v = root2[k * 16 + (n - 96)];
    }
    g_W2[idx] = v;
}

// fp32 [Nrows][K] -> packed hi/lo half2 words in permuted fragment layout
__global__ void splitpack(const float* __restrict__ src, unsigned* __restrict__ hi,
                          unsigned* __restrict__ lo, int Nrows, int K) {
    int w = blockIdx.x * blockDim.x + threadIdx.x;
    int wpr = K >> 1;
    if (w >= Nrows * wpr) return;
    int row = w / wpr, kp = w - row * wpr;
    int k = kp * 2;
    float v0 = src[(size_t)row * K + k];
    float v1 = src[(size_t)row * K + k + 1];
    __half h0 = __float2half_rn(v0), h1 = __float2half_rn(v1);
    __half l0 = __float2half_rn(v0 - __half2float(h0));
    __half l1 = __float2half_rn(v1 - __half2float(h1));
    __half2 hh = __halves2half2(h0, h1);
    __half2 ll = __halves2half2(l0, l1);
    int widx = row * wpr + ((k >> 5) << 4) + permw(k & 31);
    hi[widx] = *(unsigned*)&hh;
    lo[widx] = *(unsigned*)&ll;
}

// ---------------------------------------------------------------------------
// FP16x3 split-precision tensor-core GEMM core (templated). Same as R8-R10.
// ---------------------------------------------------------------------------
__device__ __forceinline__ void mma_fp16(float* c, unsigned a0, unsigned a1,
                                         unsigned a2, unsigned a3,
                                         unsigned b0, unsigned b1) {
    asm volatile(
        "mma.sync.aligned.m16n8k16.row.col.f32.f16.f16.f32 "
        "{%0,%1,%2,%3}, {%4,%5,%6,%7}, {%8,%9}, {%0,%1,%2,%3};"
        : "+f"(c[0]), "+f"(c[1]), "+f"(c[2]), "+f"(c[3])
        : "r"(a0), "r"(a1), "r"(a2), "r"(a3), "r"(b0), "r"(b1));
}

__device__ __forceinline__ void mma_x3(float* c,
                                       const uint4& ah0, const uint4& ah1,
                                       const uint4& al0, const uint4& al1,
                                       const uint4& bh,  const uint4& bl) {
    mma_fp16(c, ah0.x, ah1.x, ah0.y, ah1.y, bh.x, bh.y);
    mma_fp16(c, ah0.x, ah1.x, ah0.y, ah1.y, bl.x, bl.y);
    mma_fp16(c, al0.x, al1.x, al0.y, al1.y, bh.x, bh.y);
    mma_fp16(c, ah0.z, ah1.z, ah0.w, ah1.w, bh.z, bh.w);
    mma_fp16(c, ah0.z, ah1.z, ah0.w, ah1.w, bl.z, bl.w);
    mma_fp16(c, al0.z, al1.z, al0.w, al1.w, bh.z, bh.w);
}

__device__ __forceinline__ void split_store(unsigned* hi, unsigned* lo,
                                            int row, int c, float4 v) {
    __half hx0 = __float2half_rn(v.x);
    __half hx1 = __float2half_rn(v.y);
    __half hx2 = __float2half_rn(v.z);
    __half hx3 = __float2half_rn(v.w);
    __half lx0 = __float2half_rn(v.x - __half2float(hx0));
    __half lx1 = __float2half_rn(v.y - __half2float(hx1));
    __half lx2 = __float2half_rn(v.z - __half2float(hx2));
    __half lx3 = __float2half_rn(v.w - __half2float(hx3));
    int idx0 = 8 * (c & 1) + 2 * (c >> 2) + ((c >> 1) & 1);
    __half2 h01 = __halves2half2(hx0, hx1);
    __half2 h23 = __halves2half2(hx2, hx3);
    __half2 l01 = __halves2half2(lx0, lx1);
    __half2 l23 = __halves2half2(lx2, lx3);
    hi[row * 16 + idx0]     = *(unsigned*)&h01;
    hi[row * 16 + idx0 + 4] = *(unsigned*)&h23;
    lo[row * 16 + idx0]     = *(unsigned*)&l01;
    lo[row * 16 + idx0 + 4] = *(unsigned*)&l23;
}

template<int TBM, int TBN, bool APACK, int EPI>
__device__ __forceinline__ void gemm_core(
    const float* __restrict__ A,
    const unsigned* __restrict__ Ahw, const unsigned* __restrict__ Alw,
    const unsigned* __restrict__ Bhw, const unsigned* __restrict__ Blw,
    int M, int N, int K, int bm, int bn,
    int n1, const float* __restrict__ b1,
    float* __restrict__ C2, const float* __restrict__ b2,
    unsigned* __restrict__ Oh, unsigned* __restrict__ Ol) {

    __shared__ unsigned Ahi[TBM * 16], Alo[TBM * 16];
    __shared__ unsigned Bhi[TBN * 16], Blo[TBN * 16];

    constexpr int WMS = TBM / 32;
    constexpr int API = APACK ? (TBM * 4) / 256 : 1;
    constexpr int AFI = APACK ? 1 : (TBM * 8) / 256;
    constexpr int BPI = (TBN * 4) / 256;

    const int tid = threadIdx.x;
    const int wid = tid >> 5;
    const int lane = tid & 31;
    const int wm = wid % WMS;
    const int wn = wid / WMS;
    const int g = lane >> 2;
    const int t = lane & 3;
    const int wpr = K >> 1;

    float acc[2][4][4];
    #pragma unroll
    for (int i = 0; i < 2; i++)
        #pragma unroll
        for (int j = 0; j < 4; j++)
            #pragma unroll
            for (int q = 0; q < 4; q++) acc[i][j][q] = 0.0f;

    const float4 z4 = make_float4(0.f, 0.f, 0.f, 0.f);
    const uint4 zu4 = make_uint4(0, 0, 0, 0);
    uint4 pah[API], pal[API];
    float4 saf[AFI];
    uint4 pbh[BPI], pbl[BPI];

    // ---- prefetch k-tile 0 ----
    if (APACK) {
        #pragma unroll
        for (int i = 0; i < API; i++) {
            int j = tid + i * 256; int row = j >> 2, q = j & 3;
            if (bm + row < M) {
                size_t gw = (size_t)(bm + row) * wpr + q * 4;
                pah[i] = *(const uint4*)&Ahw[gw];
                pal[i] = *(const uint4*)&Alw[gw];
            } else { pah[i] = zu4; pal[i] = zu4; }
        }
    } else {
        #pragma unroll
        for (int i = 0; i < AFI; i++) {
            int j = tid + i * 256; int row = j >> 3, lc = j & 7;
            saf[i] = (bm + row < M) ? *(const float4*)(A + (size_t)(bm + row) * K + lc * 4) : z4;
        }
    }
    #pragma unroll
    for (int i = 0; i < BPI; i++) {
        int j = tid + i * 256; int row = j >> 2, q = j & 3;
        if (bn + row < N) {
            size_t gw = (size_t)(bn + row) * wpr + q * 4;
            pbh[i] = *(const uint4*)&Bhw[gw];
            pbl[i] = *(const uint4*)&Blw[gw];
        } else { pbh[i] = zu4; pbl[i] = zu4; }
    }

    for (int k0 = 0; k0 < K; k0 += 32) {
        if (APACK) {
            #pragma unroll
            for (int i = 0; i < API; i++) {
                int j = tid + i * 256; int row = j >> 2, q = j & 3;
                *(uint4*)&Ahi[row * 16 + q * 4] = pah[i];
                *(uint4*)&Alo[row * 16 + q * 4] = pal[i];
            }
        } else {
            #pragma unroll
            for (int i = 0; i < AFI; i++) {
                int j = tid + i * 256;
                split_store(Ahi, Alo, j >> 3, j & 7, saf[i]);
            }
        }
        #pragma unroll
        for (int i = 0; i < BPI; i++) {
            int j = tid + i * 256; int row = j >> 2, q = j & 3;
            *(uint4*)&Bhi[row * 16 + q * 4] = pbh[i];
            *(uint4*)&Blo[row * 16 + q * 4] = pbl[i];
        }
        __syncthreads();

        if (k0 + 32 < K) {
            int kt = ((k0 + 32) >> 5) << 4;
            if (APACK) {
                #pragma unroll
                for (int i = 0; i < API; i++) {
                    int j = tid + i * 256; int row = j >> 2, q = j & 3;
                    if (bm + row < M) {
                        size_t gw = (size_t)(bm + row) * wpr + kt + q * 4;
                        pah[i] = *(const uint4*)&Ahw[gw];
                        pal[i] = *(const uint4*)&Alw[gw];
                    } else { pah[i] = zu4; pal[i] = zu4; }
                }
            } else {
                #pragma unroll
                for (int i = 0; i < AFI; i++) {
                    int j = tid + i * 256; int row = j >> 3, lc = j & 7;
                    saf[i] = (bm + row < M) ?
                        *(const float4*)(A + (size_t)(bm + row) * K + k0 + 32 + lc * 4) : z4;
                }
            }
            #pragma unroll
            for (int i = 0; i < BPI; i++) {
                int j = tid + i * 256; int row = j >> 2, q = j & 3;
                if (bn + row < N) {
                    size_t gw = (size_t)(bn + row) * wpr + kt + q * 4;
                    pbh[i] = *(const uint4*)&Bhw[gw];
                    pbl[i] = *(const uint4*)&Blw[gw];
                } else { pbh[i] = zu4; pbl[i] = zu4; }
            }
        }

        uint4 bh[4], bl[4];
        #pragma unroll
        for (int nt = 0; nt < 4; nt++) {
            int cn = wn * 32 + nt * 8 + g;
            bh[nt] = *(const uint4*)&Bhi[cn * 16 + t * 4];
            bl[nt] = *(const uint4*)&Blo[cn * 16 + t * 4];
        }
        #pragma unroll
        for (int mt = 0; mt < 2; mt++) {
            int r = wm * 32 + mt * 16 + g;
            uint4 ah0 = *(const uint4*)&Ahi[r * 16 + t * 4];
            uint4 ah1 = *(const uint4*)&Ahi[(r + 8) * 16 + t * 4];
            uint4 al0 = *(const uint4*)&Alo[r * 16 + t * 4];
            uint4 al1 = *(const uint4*)&Alo[(r + 8) * 16 + t * 4];
            #pragma unroll
            for (int nt = 0; nt < 4; nt++)
                mma_x3(acc[mt][nt], ah0, ah1, al0, al1, bh[nt], bl[nt]);
        }
        __syncthreads();
    }

    // ---- epilogue: c0=C[g][2t], c1=C[g][2t+1], c2=C[g+8][2t], c3=C[g+8][2t+1]
    const int n2w = N - n1;
    #pragma unroll
    for (int mt = 0; mt < 2; mt++) {
        #pragma unroll
        for (int nt = 0; nt < 4; nt++) {
            int col = bn + wn * 32 + nt * 8 + 2 * t;
            if (col >= N) continue;
            #pragma unroll
            for (int half = 0; half < 2; half++) {
                int row = bm + wm * 32 + mt * 16 + g + half * 8;
                if (row >= M) continue;
                float v0 = acc[mt][nt][half * 2 + 0];
                float v1 = acc[mt][nt][half * 2 + 1];
                if (EPI == 1) {
                    v0 += b1[col]; v1 += b1[col + 1];
                    __half h0 = __float2half_rn(v0), h1 = __float2half_rn(v1);
                    __half l0 = __float2half_rn(v0 - __half2float(h0));
                    __half l1 = __float2half_rn(v1 - __half2float(h1));
                    __half2 hh = __halves2half2(h0, h1);
                    __half2 ll = __halves2half2(l0, l1);
                    int widx = row * (N >> 1) + ((col >> 5) << 4) + permw(col & 31);
                    Oh[widx] = *(unsigned*)&hh;
                    Ol[widx] = *(unsigned*)&ll;
                } else { // EPI == 2
                    if (col < n1) {
                        __half2 hv = __halves2half2(__float2half_rn(v0), __float2half_rn(v1));
                        Oh[(size_t)row * (n1 >> 1) + (col >> 1)] = *(unsigned*)&hv;
                    } else {
                        int cc = col - n1;
                        v0 += b2[cc]; v1 += b2[cc + 1];
                        *(float2*)(C2 + (size_t)row * n2w + cc) = make_float2(v0, v1);
                    }
                }
            }
        }
    }
}

// Fused input projections: A fp32, B packed, packed hi/lo output into g_xb.
__global__ __launch_bounds__(256, 2)
void gemm3_proj(const float* __restrict__ x0, const float* __restrict__ bb0,
                const float* __restrict__ x1, const float* __restrict__ bb1,
                const float* __restrict__ x2, const float* __restrict__ bb2,
                int T0, int T01) {
    int tile = blockIdx.y;
    const float* A; const float* bias;
    const unsigned *bh, *bl;
    int M, K, rowbase, ltile;
    if (tile < T0)       { A = x0; bias = bb0; bh = g_w0h; bl = g_w0l; M = N0; K = 256; rowbase = 0;       ltile = tile; }
    else if (tile < T01) { A = x1; bias = bb1; bh = g_w1h; bl = g_w1l; M = N1; K = 512; rowbase = N0;      ltile = tile - T0; }
    else                 { A = x2; bias = bb2; bh = g_w2h; bl = g_w2l; M = N2; K = 128; rowbase = N0 + N1; ltile = tile - T01; }
    gemm_core<64, 128, false, 1>(A, nullptr, nullptr, bh, bl,
        M, 128, K, ltile * 64, 0,
        128, bias, nullptr, nullptr,
        g_xbh + (size_t)rowbase * 64, g_xbl + (size_t)rowbase * 64);
}

// Layer 1: A packed (xb), B packed (W1); xt1 -> fp16, agg1 -> fp32 (+bias).
__global__ __launch_bounds__(256, 2)
void gemm_l1(const float* __restrict__ bias1) {
    gemm_core<128, 64, true, 2>(nullptr, g_xbh, g_xbl, g_W1h, g_W1l,
        NTOT, 448, 128, blockIdx.y * 128, blockIdx.x * 64,
        384, nullptr, g_agg1, bias1, g_xt1h, nullptr);
}

// Layer 2: A fp32 (agg1), B packed (W2); xt2 -> fp16, agg2 -> fp32 (+bias).
__global__ __launch_bounds__(256, 2)
void gemm_l2(const float* __restrict__ bias2) {
    gemm_core<128, 64, false, 2>(g_agg1, nullptr, nullptr, g_W2h, g_W2l,
        NTOT, 112, 64, blockIdx.y * 128, blockIdx.x * 64,
        96, nullptr, g_agg2, bias2, g_xt2h, nullptr);
}

// ---------------------------------------------------------------------------
// CSR segmented reduction (atomic-free aggregation)
// ---------------------------------------------------------------------------
// Layer 1: one warp per dst; lane owns cols 2*lane, 2*lane+1 (one half2/edge).
__global__ __launch_bounds__(256)
void reduce64_kernel() {
    int warp = (blockIdx.x * 256 + threadIdx.x) >> 5;
    int lane = threadIdx.x & 31;
    if (warp >= NTOT) return;
    int d = warp;
    float t0 = 0.f, t1 = 0.f;
    #pragma unroll
    for (int r = 0; r < NR; r++) {
        int seg = r * NTOT + d;
        int n = g_cnt[seg];
        if (n == 0) continue;
        int beg = g_off[seg];
        float a0 = 0.f, a1 = 0.f;
        for (int j = beg; j < beg + n; j++) {
            int s = g_psrc[j];
            unsigned hw = g_xt1h[(size_t)s * 192 + r * 32 + lane];
            float2 f = __half22float2(*(__half2*)&hw);
            a0 += f.x; a1 += f.y;
        }
        float w = 1.0f / (float)n;
        t0 += a0 * w; t1 += a1 * w;
    }
    float2* p = (float2*)(g_agg1 + (size_t)d * 64 + 2 * lane);
    float2 cur = *p;
    cur.x += t0; cur.y += t1;
    *p = cur;
}

// Layer 2: 8 lanes per dst (4 dst/warp); lane owns cols 2*l8, 2*l8+1.
__global__ __launch_bounds__(256)
void reduce16_kernel() {
    int tglob = blockIdx.x * 256 + threadIdx.x;
    int d = tglob >> 3;
    int l8 = tglob & 7;
    if (d >= NTOT) return;
    float t0 = 0.f, t1 = 0.f;
    #pragma unroll
    for (int r = 0; r < NR; r++) {
        int seg = r * NTOT + d;
        int n = g_cnt[seg];
        if (n == 0) continue;
        int beg = g_off[seg];
        float a0 = 0.f, a1 = 0.f;
        for (int j = beg; j < beg + n; j++) {
            int s = g_psrc[j];
            unsigned hw = g_xt2h[(size_t)s * 48 + r * 8 + l8];
            float2 f = __half22float2(*(__half2*)&hw);
            a0 += f.x; a1 += f.y;
        }
        float w = 1.0f / (float)n;
        t0 += a0 * w; t1 += a1 * w;
    }
    float2* p = (float2*)(g_agg2 + (size_t)d * 16 + 2 * l8);
    float2 cur = *p;
    cur.x += t0; cur.y += t1;
    *p = cur;
}

// ---------------------------------------------------------------------------
// Softmax over the first N0 rows (16 cols each)
// ---------------------------------------------------------------------------
__global__ void softmax_kernel(float* __restrict__ out) {
    int row = blockIdx.x * blockDim.x + threadIdx.x;
    if (row >= N0) return;
    const float* p = g_agg2 + (size_t)row * 16;
    float v[16];
    #pragma unroll
    for (int i = 0; i < 4; i++) {
        float4 q = *(const float4*)(p + i * 4);
        v[i * 4 + 0] = q.x; v[i * 4 + 1] = q.y; v[i * 4 + 2] = q.z; v[i * 4 + 3] = q.w;
    }
    float mx = v[0];
    #pragma unroll
    for (int i = 1; i < 16; i++) mx = fmaxf(mx, v[i]);
    float s = 0.0f;
    #pragma unroll
    for (int i = 0; i < 16; i++) { v[i] = expf(v[i] - mx); s += v[i]; }
    float inv = 1.0f / s;
    float* o = out + (size_t)row * 16;
    #pragma unroll
    for (int i = 0; i < 4; i++) {
        float4 q = make_float4(v[i * 4 + 0] * inv, v[i * 4 + 1] * inv,
                               v[i * 4 + 2] * inv, v[i * 4 + 3] * inv);
        *(float4*)(o + i * 4) = q;
    }
}

// ---------------------------------------------------------------------------
// Launcher
// ---------------------------------------------------------------------------
extern "C" void kernel_launch(void* const* d_in, const int* in_sizes, int n_in,
                              void* d_out, int out_size) {
    (void)in_sizes; (void)n_in; (void)out_size;
    const float* x0     = (const float*)d_in[0];
    const float* x1     = (const float*)d_in[1];
    const float* x2     = (const float*)d_in[2];
    const float* lin_w0 = (const float*)d_in[3];
    const float* lin_b0 = (const float*)d_in[4];
    const float* lin_w1 = (const float*)d_in[5];
    const float* lin_b1 = (const float*)d_in[6];
    const float* lin_w2 = (const float*)d_in[7];
    const float* lin_b2 = (const float*)d_in[8];
    const float* bases1 = (const float*)d_in[9];
    const float* comp1  = (const float*)d_in[10];
    const float* root1  = (const float*)d_in[11];
    const float* bias1  = (const float*)d_in[12];
    const float* bases2 = (const float*)d_in[13];
    const float* comp2  = (const float*)d_in[14];
    const float* root2  = (const float*)d_in[15];
    const float* bias2  = (const float*)d_in[16];
    const int*   eidx   = (const int*)d_in[17];
    const int*   etyp   = (const int*)d_in[18];
    float* out = (float*)d_out;

    float *W1f, *W2f;
    unsigned *w0h, *w0l, *w1h, *w1l, *w2h, *w2l, *W1h, *W1l, *W2h, *W2l;
    cudaGetSymbolAddress((void**)&W1f, g_W1);
    cudaGetSymbolAddress((void**)&W2f, g_W2);
    cudaGetSymbolAddress((void**)&w0h, g_w0h); cudaGetSymbolAddress((void**)&w0l, g_w0l);
    cudaGetSymbolAddress((void**)&w1h, g_w1h); cudaGetSymbolAddress((void**)&w1l, g_w1l);
    cudaGetSymbolAddress((void**)&w2h, g_w2h); cudaGetSymbolAddress((void**)&w2l, g_w2l);
    cudaGetSymbolAddress((void**)&W1h, g_W1h); cudaGetSymbolAddress((void**)&W1l, g_W1l);
    cudaGetSymbolAddress((void**)&W2h, g_W2h); cudaGetSymbolAddress((void**)&W2l, g_W2l);

    // CSR build: counts -> offsets -> slot fill (shared by both layers)
    zero_cnt_kernel<<<(RN + 255) / 256, 256>>>();
    count_kernel<<<(NE + 255) / 256, 256>>>(eidx + NE, etyp);
    alloc_kernel<<<(RN + 255) / 256, 256>>>();
    fill_kernel<<<(NE + 255) / 256, 256>>>(eidx, etyp);

    // pre-split weights into packed hi/lo fragment layout
    splitpack<<<(128 * 128 + 255) / 256, 256>>>(lin_w0, w0h, w0l, 128, 256);
    splitpack<<<(128 * 256 + 255) / 256, 256>>>(lin_w1, w1h, w1l, 128, 512);
    splitpack<<<(128 * 64  + 255) / 256, 256>>>(lin_w2, w2h, w2l, 128, 128);
    build_w1<<<(448 * 128 + 255) / 256, 256>>>(comp1, bases1, root1);
    splitpack<<<(448 * 64 + 255) / 256, 256>>>(W1f, W1h, W1l, 448, 128);
    build_w2<<<(112 * 64 + 255) / 256, 256>>>(comp2, bases2, root2);
    splitpack<<<(112 * 32 + 255) / 256, 256>>>(W2f, W2h, W2l, 112, 64);

    // typed input projections -> packed xb (fused single launch)
    const int T0 = (N0 + 63) / 64;
    const int T1 = (N1 + 63) / 64;
    const int T2 = (N2 + 63) / 64;
    gemm3_proj<<<dim3(1, T0 + T1 + T2), 256>>>(x0, lin_b0, x1, lin_b1, x2, lin_b2,
                                               T0, T0 + T1);

    // layer 1: xt1 (fp16 relation cols) + agg1 init (root+bias), then reduce
    gemm_l1<<<dim3(7, (NTOT + 127) / 128), 256>>>(bias1);
    reduce64_kernel<<<(NTOT * 32 + 255) / 256, 256>>>();

    // layer 2: xt2 (fp16) + agg2 init, then reduce
    gemm_l2<<<dim3(2, (NTOT + 127) / 128), 256>>>(bias2);
    reduce16_kernel<<<(NTOT * 8 + 255) / 256, 256>>>();

    // softmax over author rows
    softmax_kernel<<<(N0 + 255) / 256, 256>>>(out);
}

// round 12
// speedup vs baseline: 1.0806x; 1.0454x over previous
#include <cuda_runtime.h>
#include <cuda_fp16.h>
#include <cstdint>
#include <math.h>

// Problem constants (fixed by the dataset)
#define N0 30000
#define N1 50000
#define N2 20000
#define NTOT 100000
#define NE 1600000
#define NR 6
#define RN (NR * NTOT)

// ---------------------------------------------------------------------------
// Scratch (static __device__ globals; allocation-free per harness rules)
// ---------------------------------------------------------------------------
__device__ unsigned g_xbh[(size_t)NTOT * 64];   // packed hi: proj output (K=128)
__device__ unsigned g_xbl[(size_t)NTOT * 64];   // packed lo
__device__ unsigned g_xt1h[(size_t)NTOT * 192]; // layer1 transform, fp16 half2 [N][384]
__device__ float    g_agg1[(size_t)NTOT * 64];  // layer1 accumulator / h1 (fp32)
__device__ unsigned g_xt2h[(size_t)NTOT * 48];  // layer2 transform, fp16 half2 [N][96]
__device__ float    g_agg2[(size_t)NTOT * 16];  // layer2 accumulator / h2 (fp32)
__device__ int   g_cnt[RN];                     // per (r,dst) edge counts
__device__ int   g_off[RN];                     // segment base slot
__device__ int   g_cur[RN];                     // fill cursors
__device__ int   g_psrc[NE];                    // src node per slot (CSR payload)
__device__ int   g_total;                       // slot allocator
__device__ float g_W1[448 * 128];               // fp32 [n][k] (intermediate)
__device__ float g_W2[112 * 64];
// packed weights (hi/lo half2 words, permuted fragment layout)
__device__ unsigned g_w0h[128 * 128], g_w0l[128 * 128];   // lin_w0: 128x256
__device__ unsigned g_w1h[128 * 256], g_w1l[128 * 256];   // lin_w1: 128x512
__device__ unsigned g_w2h[128 * 64],  g_w2l[128 * 64];    // lin_w2: 128x128
__device__ unsigned g_W1h[448 * 64],  g_W1l[448 * 64];    // W1: 448x128
__device__ unsigned g_W2h[112 * 32],  g_W2l[112 * 32];    // W2: 112x64

// permuted half2-word index within a 32-col k-tile (kk even, in [0,32))
__device__ __forceinline__ int permw(int kk) {
    int c = kk >> 2;
    int idx0 = 8 * (c & 1) + 2 * (c >> 2) + ((c >> 1) & 1);
    return idx0 + ((kk >> 1) & 1) * 4;
}

// ---------------------------------------------------------------------------
// Graph preprocessing: counts -> segment offsets -> CSR fill
// ---------------------------------------------------------------------------
__global__ void zero_cnt_kernel() {
    int i = blockIdx.x * blockDim.x + threadIdx.x;
    if (i == 0) g_total = 0;
    if (i < RN) g_cnt[i] = 0;
}

__global__ void count_kernel(const int* __restrict__ dst, const int* __restrict__ et) {
    int e = blockIdx.x * blockDim.x + threadIdx.x;
    if (e < NE) atomicAdd(&g_cnt[et[e] * NTOT + dst[e]], 1);
}

// Block-aggregated slot allocation: exclusive prefix within block, one
// atomicAdd on g_total per 256 segments.
__global__ void alloc_kernel() {
    __shared__ int warp_sums[8];
    __shared__ int block_base;
    int i = blockIdx.x * 256 + threadIdx.x;
    int lane = threadIdx.x & 31, w = threadIdx.x >> 5;
    int c = (i < RN) ? g_cnt[i] : 0;
    int x = c;
    #pragma unroll
    for (int o = 1; o < 32; o <<= 1) {
        int y = __shfl_up_sync(0xffffffffu, x, o);
        if (lane >= o) x += y;
    }
    if (lane == 31) warp_sums[w] = x;
    __syncthreads();
    if (threadIdx.x < 8) {
        int v = warp_sums[threadIdx.x];
        #pragma unroll
        for (int o = 1; o < 8; o <<= 1) {
            int y = __shfl_up_sync(0xffu, v, o);
            if ((int)threadIdx.x >= o) v += y;
        }
        warp_sums[threadIdx.x] = v;
        if (threadIdx.x == 7) block_base = atomicAdd(&g_total, v);
    }
    __syncthreads();
    int base = block_base + (w ? warp_sums[w - 1] : 0) + x - c;
    if (i < RN) { g_off[i] = base; g_cur[i] = base; }
}

__global__ void fill_kernel(const int* __restrict__ ei, const int* __restrict__ et) {
    int e = blockIdx.x * blockDim.x + threadIdx.x;
    if (e >= NE) return;
    int s = ei[e];
    int d = ei[NE + e];
    int r = et[e];
    int pos = atomicAdd(&g_cur[r * NTOT + d], 1);
    g_psrc[pos] = s;
}

// ---------------------------------------------------------------------------
// Weight-building helpers
// ---------------------------------------------------------------------------
__global__ void build_w1(const float* __restrict__ comp1, const float* __restrict__ bases1,
                         const float* __restrict__ root1) {
    int idx = blockIdx.x * blockDim.x + threadIdx.x;
    if (idx >= 448 * 128) return;
    int n = idx >> 7, k = idx & 127;
    float v;
    if (n < 384) {
        int r = n >> 6, o = n & 63;
        v = 0.0f;
        for (int b = 0; b < 30; b++)
            v += comp1[r * 30 + b] * bases1[((size_t)b * 128 + k) * 64 + o];
    } else {
        v = root1[k * 64 + (n - 384)];
    }
    g_W1[idx] = v;
}

__global__ void build_w2(const float* __restrict__ comp2, const float* __restrict__ bases2,
                         const float* __restrict__ root2) {
    int idx = blockIdx.x * blockDim.x + threadIdx.x;
    if (idx >= 112 * 64) return;
    int n = idx >> 6, k = idx & 63;
    float v;
    if (n < 96) {
        int r = n >> 4, o = n & 15;
        v = 0.0f;
        for (int b = 0; b < 30; b++)
            v += comp2[r * 30 + b] * bases2[((size_t)b * 64 + k) * 16 + o];
    } else {
        v = root2[k * 16 + (n - 96)];
    }
    g_W2[idx] = v;
}

// fp32 [Nrows][K] -> packed hi/lo half2 words in permuted fragment layout
__global__ void splitpack(const float* __restrict__ src, unsigned* __restrict__ hi,
                          unsigned* __restrict__ lo, int Nrows, int K) {
    int w = blockIdx.x * blockDim.x + threadIdx.x;
    int wpr = K >> 1;
    if (w >= Nrows * wpr) return;
    int row = w / wpr, kp = w - row * wpr;
    int k = kp * 2;
    float v0 = src[(size_t)row * K + k];
    float v1 = src[(size_t)row * K + k + 1];
    __half h0 = __float2half_rn(v0), h1 = __float2half_rn(v1);
    __half l0 = __float2half_rn(v0 - __half2float(h0));
    __half l1 = __float2half_rn(v1 - __half2float(h1));
    __half2 hh = __halves2half2(h0, h1);
    __half2 ll = __halves2half2(l0, l1);
    int widx = row * wpr + ((k >> 5) << 4) + permw(k & 31);
    hi[widx] = *(unsigned*)&hh;
    lo[widx] = *(unsigned*)&ll;
}

// ---------------------------------------------------------------------------
// FP16x3 split-precision tensor-core GEMM core (templated).
//   C[m,n] = sum_k A[m,k]*Bw[n,k]; a*b ~= ahi*bhi + ahi*blo + alo*bhi.
// 256 threads = 8 warps, 32x32 warptile.
// NEW (R12): double-buffered smem, ONE __syncthreads per 32-k tile.
// ---------------------------------------------------------------------------
__device__ __forceinline__ void mma_fp16(float* c, unsigned a0, unsigned a1,
                                         unsigned a2, unsigned a3,
                                         unsigned b0, unsigned b1) {
    asm volatile(
        "mma.sync.aligned.m16n8k16.row.col.f32.f16.f16.f32 "
        "{%0,%1,%2,%3}, {%4,%5,%6,%7}, {%8,%9}, {%0,%1,%2,%3};"
        : "+f"(c[0]), "+f"(c[1]), "+f"(c[2]), "+f"(c[3])
        : "r"(a0), "r"(a1), "r"(a2), "r"(a3), "r"(b0), "r"(b1));
}

__device__ __forceinline__ void mma_x3(float* c,
                                       const uint4& ah0, const uint4& ah1,
                                       const uint4& al0, const uint4& al1,
                                       const uint4& bh,  const uint4& bl) {
    mma_fp16(c, ah0.x, ah1.x, ah0.y, ah1.y, bh.x, bh.y);
    mma_fp16(c, ah0.x, ah1.x, ah0.y, ah1.y, bl.x, bl.y);
    mma_fp16(c, al0.x, al1.x, al0.y, al1.y, bh.x, bh.y);
    mma_fp16(c, ah0.z, ah1.z, ah0.w, ah1.w, bh.z, bh.w);
    mma_fp16(c, ah0.z, ah1.z, ah0.w, ah1.w, bl.z, bl.w);
    mma_fp16(c, al0.z, al1.z, al0.w, al1.w, bh.z, bh.w);
}

__device__ __forceinline__ void split_store(unsigned* hi, unsigned* lo,
                                            int row, int c, float4 v) {
    __half hx0 = __float2half_rn(v.x);
    __half hx1 = __float2half_rn(v.y);
    __half hx2 = __float2half_rn(v.z);
    __half hx3 = __float2half_rn(v.w);
    __half lx0 = __float2half_rn(v.x - __half2float(hx0));
    __half lx1 = __float2half_rn(v.y - __half2float(hx1));
    __half lx2 = __float2half_rn(v.z - __half2float(hx2));
    __half lx3 = __float2half_rn(v.w - __half2float(hx3));
    int idx0 = 8 * (c & 1) + 2 * (c >> 2) + ((c >> 1) & 1);
    __half2 h01 = __halves2half2(hx0, hx1);
    __half2 h23 = __halves2half2(hx2, hx3);
    __half2 l01 = __halves2half2(lx0, lx1);
    __half2 l23 = __halves2half2(lx2, lx3);
    hi[row * 16 + idx0]     = *(unsigned*)&h01;
    hi[row * 16 + idx0 + 4] = *(unsigned*)&h23;
    lo[row * 16 + idx0]     = *(unsigned*)&l01;
    lo[row * 16 + idx0 + 4] = *(unsigned*)&l23;
}

template<int TBM, int TBN, bool APACK, int EPI>
__device__ __forceinline__ void gemm_core(
    const float* __restrict__ A,
    const unsigned* __restrict__ Ahw, const unsigned* __restrict__ Alw,
    const unsigned* __restrict__ Bhw, const unsigned* __restrict__ Blw,
    int M, int N, int K, int bm, int bn,
    int n1, const float* __restrict__ b1,
    float* __restrict__ C2, const float* __restrict__ b2,
    unsigned* __restrict__ Oh, unsigned* __restrict__ Ol) {

    // double-buffered tiles: 2 * (TBM+TBN) * 16 words * 2 arrays = 48 KB total
    __shared__ unsigned Ahi[2][TBM * 16], Alo[2][TBM * 16];
    __shared__ unsigned Bhi[2][TBN * 16], Blo[2][TBN * 16];

    constexpr int WMS = TBM / 32;
    constexpr int API = APACK ? (TBM * 4) / 256 : 1;
    constexpr int AFI = APACK ? 1 : (TBM * 8) / 256;
    constexpr int BPI = (TBN * 4) / 256;

    const int tid = threadIdx.x;
    const int wid = tid >> 5;
    const int lane = tid & 31;
    const int wm = wid % WMS;
    const int wn = wid / WMS;
    const int g = lane >> 2;
    const int t = lane & 3;
    const int wpr = K >> 1;

    float acc[2][4][4];
    #pragma unroll
    for (int i = 0; i < 2; i++)
        #pragma unroll
        for (int j = 0; j < 4; j++)
            #pragma unroll
            for (int q = 0; q < 4; q++) acc[i][j][q] = 0.0f;

    const float4 z4 = make_float4(0.f, 0.f, 0.f, 0.f);
    const uint4 zu4 = make_uint4(0, 0, 0, 0);
    uint4 pah[API], pal[API];
    float4 saf[AFI];
    uint4 pbh[BPI], pbl[BPI];

    auto ldA = [&](int k0) {
        if (APACK) {
            int ktw = (k0 >> 5) << 4;
            #pragma unroll
            for (int i = 0; i < API; i++) {
                int j = tid + i * 256; int row = j >> 2, q = j & 3;
                if (bm + row < M) {
                    size_t gw = (size_t)(bm + row) * wpr + ktw + q * 4;
                    pah[i] = *(const uint4*)&Ahw[gw];
                    pal[i] = *(const uint4*)&Alw[gw];
                } else { pah[i] = zu4; pal[i] = zu4; }
            }
        } else {
            #pragma unroll
            for (int i = 0; i < AFI; i++) {
                int j = tid + i * 256; int row = j >> 3, lc = j & 7;
                saf[i] = (bm + row < M) ?
                    *(const float4*)(A + (size_t)(bm + row) * K + k0 + lc * 4) : z4;
            }
        }
    };
    auto ldB = [&](int k0) {
        int ktw = (k0 >> 5) << 4;
        #pragma unroll
        for (int i = 0; i < BPI; i++) {
            int j = tid + i * 256; int row = j >> 2, q = j & 3;
            if (bn + row < N) {
                size_t gw = (size_t)(bn + row) * wpr + ktw + q * 4;
                pbh[i] = *(const uint4*)&Bhw[gw];
                pbl[i] = *(const uint4*)&Blw[gw];
            } else { pbh[i] = zu4; pbl[i] = zu4; }
        }
    };
    auto stA = [&](int buf) {
        if (APACK) {
            #pragma unroll
            for (int i = 0; i < API; i++) {
                int j = tid + i * 256; int row = j >> 2, q = j & 3;
                *(uint4*)&Ahi[buf][row * 16 + q * 4] = pah[i];
                *(uint4*)&Alo[buf][row * 16 + q * 4] = pal[i];
            }
        } else {
            #pragma unroll
            for (int i = 0; i < AFI; i++) {
                int j = tid + i * 256;
                split_store(Ahi[buf], Alo[buf], j >> 3, j & 7, saf[i]);
            }
        }
    };
    auto stB = [&](int buf) {
        #pragma unroll
        for (int i = 0; i < BPI; i++) {
            int j = tid + i * 256; int row = j >> 2, q = j & 3;
            *(uint4*)&Bhi[buf][row * 16 + q * 4] = pbh[i];
            *(uint4*)&Blo[buf][row * 16 + q * 4] = pbl[i];
        }
    };

    // prologue: tile 0 into buffer 0
    ldA(0); ldB(0);
    stA(0); stB(0);
    __syncthreads();

    const int nk = K >> 5;
    for (int it = 0; it < nk; it++) {
        const int cur = it & 1;
        const bool more = (it + 1) < nk;
        if (more) { ldA((it + 1) << 5); ldB((it + 1) << 5); }

        uint4 bh[4], bl[4];
        #pragma unroll
        for (int nt = 0; nt < 4; nt++) {
            int cn = wn * 32 + nt * 8 + g;
            bh[nt] = *(const uint4*)&Bhi[cur][cn * 16 + t * 4];
            bl[nt] = *(const uint4*)&Blo[cur][cn * 16 + t * 4];
        }
        #pragma unroll
        for (int mt = 0; mt < 2; mt++) {
            int r = wm * 32 + mt * 16 + g;
            uint4 ah0 = *(const uint4*)&Ahi[cur][r * 16 + t * 4];
            uint4 ah1 = *(const uint4*)&Ahi[cur][(r + 8) * 16 + t * 4];
            uint4 al0 = *(const uint4*)&Alo[cur][r * 16 + t * 4];
            uint4 al1 = *(const uint4*)&Alo[cur][(r + 8) * 16 + t * 4];
            #pragma unroll
            for (int nt = 0; nt < 4; nt++)
                mma_x3(acc[mt][nt], ah0, ah1, al0, al1, bh[nt], bl[nt]);
        }
        if (more) {
            stA(cur ^ 1); stB(cur ^ 1);
            __syncthreads();
        }
    }

    // ---- epilogue: c0=C[g][2t], c1=C[g][2t+1], c2=C[g+8][2t], c3=C[g+8][2t+1]
    const int n2w = N - n1;
    #pragma unroll
    for (int mt = 0; mt < 2; mt++) {
        #pragma unroll
        for (int nt = 0; nt < 4; nt++) {
            int col = bn + wn * 32 + nt * 8 + 2 * t;
            if (col >= N) continue;
            #pragma unroll
            for (int half = 0; half < 2; half++) {
                int row = bm + wm * 32 + mt * 16 + g + half * 8;
                if (row >= M) continue;
                float v0 = acc[mt][nt][half * 2 + 0];
                float v1 = acc[mt][nt][half * 2 + 1];
                if (EPI == 1) {
                    v0 += b1[col]; v1 += b1[col + 1];
                    __half h0 = __float2half_rn(v0), h1 = __float2half_rn(v1);
                    __half l0 = __float2half_rn(v0 - __half2float(h0));
                    __half l1 = __float2half_rn(v1 - __half2float(h1));
                    __half2 hh = __halves2half2(h0, h1);
                    __half2 ll = __halves2half2(l0, l1);
                    int widx = row * (N >> 1) + ((col >> 5) << 4) + permw(col & 31);
                    Oh[widx] = *(unsigned*)&hh;
                    Ol[widx] = *(unsigned*)&ll;
                } else { // EPI == 2
                    if (col < n1) {
                        __half2 hv = __halves2half2(__float2half_rn(v0), __float2half_rn(v1));
                        Oh[(size_t)row * (n1 >> 1) + (col >> 1)] = *(unsigned*)&hv;
                    } else {
                        int cc = col - n1;
                        v0 += b2[cc]; v1 += b2[cc + 1];
                        *(float2*)(C2 + (size_t)row * n2w + cc) = make_float2(v0, v1);
                    }
                }
            }
        }
    }
}

// Fused input projections: A fp32, B packed, packed hi/lo output into g_xb.
__global__ __launch_bounds__(256, 2)
void gemm3_proj(const float* __restrict__ x0, const float* __restrict__ bb0,
                const float* __restrict__ x1, const float* __restrict__ bb1,
                const float* __restrict__ x2, const float* __restrict__ bb2,
                int T0, int T01) {
    int tile = blockIdx.y;
    const float* A; const float* bias;
    const unsigned *bh, *bl;
    int M, K, rowbase, ltile;
    if (tile < T0)       { A = x0; bias = bb0; bh = g_w0h; bl = g_w0l; M = N0; K = 256; rowbase = 0;       ltile = tile; }
    else if (tile < T01) { A = x1; bias = bb1; bh = g_w1h; bl = g_w1l; M = N1; K = 512; rowbase = N0;      ltile = tile - T0; }
    else                 { A = x2; bias = bb2; bh = g_w2h; bl = g_w2l; M = N2; K = 128; rowbase = N0 + N1; ltile = tile - T01; }
    gemm_core<64, 128, false, 1>(A, nullptr, nullptr, bh, bl,
        M, 128, K, ltile * 64, 0,
        128, bias, nullptr, nullptr,
        g_xbh + (size_t)rowbase * 64, g_xbl + (size_t)rowbase * 64);
}

// Layer 1: A packed (xb), B packed (W1); xt1 -> fp16, agg1 -> fp32 (+bias).
__global__ __launch_bounds__(256, 2)
void gemm_l1(const float* __restrict__ bias1) {
    gemm_core<128, 64, true, 2>(nullptr, g_xbh, g_xbl, g_W1h, g_W1l,
        NTOT, 448, 128, blockIdx.y * 128, blockIdx.x * 64,
        384, nullptr, g_agg1, bias1, g_xt1h, nullptr);
}

// Layer 2: A fp32 (agg1), B packed (W2); xt2 -> fp16, agg2 -> fp32 (+bias).
__global__ __launch_bounds__(256, 2)
void gemm_l2(const float* __restrict__ bias2) {
    gemm_core<128, 64, false, 2>(g_agg1, nullptr, nullptr, g_W2h, g_W2l,
        NTOT, 112, 64, blockIdx.y * 128, blockIdx.x * 64,
        96, nullptr, g_agg2, bias2, g_xt2h, nullptr);
}

// ---------------------------------------------------------------------------
// CSR segmented reduction (atomic-free aggregation)
// ---------------------------------------------------------------------------
// Layer 1: one warp per dst; lane owns cols 2*lane, 2*lane+1 (one half2/edge).
__global__ __launch_bounds__(256)
void reduce64_kernel() {
    int warp = (blockIdx.x * 256 + threadIdx.x) >> 5;
    int lane = threadIdx.x & 31;
    if (warp >= NTOT) return;
    int d = warp;
    float t0 = 0.f, t1 = 0.f;
    #pragma unroll
    for (int r = 0; r < NR; r++) {
        int seg = r * NTOT + d;
        int n = g_cnt[seg];
        if (n == 0) continue;
        int beg = g_off[seg];
        float a0 = 0.f, a1 = 0.f;
        for (int j = beg; j < beg + n; j++) {
            int s = g_psrc[j];
            unsigned hw = g_xt1h[(size_t)s * 192 + r * 32 + lane];
            float2 f = __half22float2(*(__half2*)&hw);
            a0 += f.x; a1 += f.y;
        }
        float w = 1.0f / (float)n;
        t0 += a0 * w; t1 += a1 * w;
    }
    float2* p = (float2*)(g_agg1 + (size_t)d * 64 + 2 * lane);
    float2 cur = *p;
    cur.x += t0; cur.y += t1;
    *p = cur;
}

// Layer 2: 8 lanes per dst (4 dst/warp); only dst < N0 feeds the output.
__global__ __launch_bounds__(256)
void reduce16_kernel() {
    int tglob = blockIdx.x * 256 + threadIdx.x;
    int d = tglob >> 3;
    int l8 = tglob & 7;
    if (d >= N0) return;
    float t0 = 0.f, t1 = 0.f;
    #pragma unroll
    for (int r = 0; r < NR; r++) {
        int seg = r * NTOT + d;
        int n = g_cnt[seg];
        if (n == 0) continue;
        int beg = g_off[seg];
        float a0 = 0.f, a1 = 0.f;
        for (int j = beg; j < beg + n; j++) {
            int s = g_psrc[j];
            unsigned hw = g_xt2h[(size_t)s * 48 + r * 8 + l8];
            float2 f = __half22float2(*(__half2*)&hw);
            a0 += f.x; a1 += f.y;
        }
        float w = 1.0f / (float)n;
        t0 += a0 * w; t1 += a1 * w;
    }
    float2* p = (float2*)(g_agg2 + (size_t)d * 16 + 2 * l8);
    float2 cur = *p;
    cur.x += t0; cur.y += t1;
    *p = cur;
}

// ---------------------------------------------------------------------------
// Softmax over the first N0 rows (16 cols each)
// ---------------------------------------------------------------------------
__global__ void softmax_kernel(float* __restrict__ out) {
    int row = blockIdx.x * blockDim.x + threadIdx.x;
    if (row >= N0) return;
    const float* p = g_agg2 + (size_t)row * 16;
    float v[16];
    #pragma unroll
    for (int i = 0; i < 4; i++) {
        float4 q = *(const float4*)(p + i * 4);
        v[i * 4 + 0] = q.x; v[i * 4 + 1] = q.y; v[i * 4 + 2] = q.z; v[i * 4 + 3] = q.w;
    }
    float mx = v[0];
    #pragma unroll
    for (int i = 1; i < 16; i++) mx = fmaxf(mx, v[i]);
    float s = 0.0f;
    #pragma unroll
    for (int i = 0; i < 16; i++) { v[i] = expf(v[i] - mx); s += v[i]; }
    float inv = 1.0f / s;
    float* o = out + (size_t)row * 16;
    #pragma unroll
    for (int i = 0; i < 4; i++) {
        float4 q = make_float4(v[i * 4 + 0] * inv, v[i * 4 + 1] * inv,
                               v[i * 4 + 2] * inv, v[i * 4 + 3] * inv);
        *(float4*)(o + i * 4) = q;
    }
}

// ---------------------------------------------------------------------------
// Launcher
// ---------------------------------------------------------------------------
extern "C" void kernel_launch(void* const* d_in, const int* in_sizes, int n_in,
                              void* d_out, int out_size) {
    (void)in_sizes; (void)n_in; (void)out_size;
    const float* x0     = (const float*)d_in[0];
    const float* x1     = (const float*)d_in[1];
    const float* x2     = (const float*)d_in[2];
    const float* lin_w0 = (const float*)d_in[3];
    const float* lin_b0 = (const float*)d_in[4];
    const float* lin_w1 = (const float*)d_in[5];
    const float* lin_b1 = (const float*)d_in[6];
    const float* lin_w2 = (const float*)d_in[7];
    const float* lin_b2 = (const float*)d_in[8];
    const float* bases1 = (const float*)d_in[9];
    const float* comp1  = (const float*)d_in[10];
    const float* root1  = (const float*)d_in[11];
    const float* bias1  = (const float*)d_in[12];
    const float* bases2 = (const float*)d_in[13];
    const float* comp2  = (const float*)d_in[14];
    const float* root2  = (const float*)d_in[15];
    const float* bias2  = (const float*)d_in[16];
    const int*   eidx   = (const int*)d_in[17];
    const int*   etyp   = (const int*)d_in[18];
    float* out = (float*)d_out;

    float *W1f, *W2f;
    unsigned *w0h, *w0l, *w1h, *w1l, *w2h, *w2l, *W1h, *W1l, *W2h, *W2l;
    cudaGetSymbolAddress((void**)&W1f, g_W1);
    cudaGetSymbolAddress((void**)&W2f, g_W2);
    cudaGetSymbolAddress((void**)&w0h, g_w0h); cudaGetSymbolAddress((void**)&w0l, g_w0l);
    cudaGetSymbolAddress((void**)&w1h, g_w1h); cudaGetSymbolAddress((void**)&w1l, g_w1l);
    cudaGetSymbolAddress((void**)&w2h, g_w2h); cudaGetSymbolAddress((void**)&w2l, g_w2l);
    cudaGetSymbolAddress((void**)&W1h, g_W1h); cudaGetSymbolAddress((void**)&W1l, g_W1l);
    cudaGetSymbolAddress((void**)&W2h, g_W2h); cudaGetSymbolAddress((void**)&W2l, g_W2l);

    // CSR build: counts -> offsets -> slot fill (shared by both layers)
    zero_cnt_kernel<<<(RN + 255) / 256, 256>>>();
    count_kernel<<<(NE + 255) / 256, 256>>>(eidx + NE, etyp);
    alloc_kernel<<<(RN + 255) / 256, 256>>>();
    fill_kernel<<<(NE + 255) / 256, 256>>>(eidx, etyp);

    // pre-split weights into packed hi/lo fragment layout
    splitpack<<<(128 * 128 + 255) / 256, 256>>>(lin_w0, w0h, w0l, 128, 256);
    splitpack<<<(128 * 256 + 255) / 256, 256>>>(lin_w1, w1h, w1l, 128, 512);
    splitpack<<<(128 * 64  + 255) / 256, 256>>>(lin_w2, w2h, w2l, 128, 128);
    build_w1<<<(448 * 128 + 255) / 256, 256>>>(comp1, bases1, root1);
    splitpack<<<(448 * 64 + 255) / 256, 256>>>(W1f, W1h, W1l, 448, 128);
    build_w2<<<(112 * 64 + 255) / 256, 256>>>(comp2, bases2, root2);
    splitpack<<<(112 * 32 + 255) / 256, 256>>>(W2f, W2h, W2l, 112, 64);

    // typed input projections -> packed xb (fused single launch)
    const int T0 = (N0 + 63) / 64;
    const int T1 = (N1 + 63) / 64;
    const int T2 = (N2 + 63) / 64;
    gemm3_proj<<<dim3(1, T0 + T1 + T2), 256>>>(x0, lin_b0, x1, lin_b1, x2, lin_b2,
                                               T0, T0 + T1);

    // layer 1: xt1 (fp16 relation cols) + agg1 init (root+bias), then reduce
    gemm_l1<<<dim3(7, (NTOT + 127) / 128), 256>>>(bias1);
    reduce64_kernel<<<(NTOT * 32 + 255) / 256, 256>>>();

    // layer 2: xt2 (fp16) + agg2 init, then reduce (output rows only)
    gemm_l2<<<dim3(2, (NTOT + 127) / 128), 256>>>(bias2);
    reduce16_kernel<<<(N0 * 8 + 255) / 256, 256>>>();

    // softmax over author rows
    softmax_kernel<<<(N0 + 255) / 256, 256>>>(out);
}

// round 13
// speedup vs baseline: 1.1505x; 1.0647x over previous
#include <cuda_runtime.h>
#include <cuda_fp16.h>
#include <cstdint>
#include <math.h>

// Problem constants (fixed by the dataset)
#define N0 30000
#define N1 50000
#define N2 20000
#define NTOT 100000
#define NE 1600000
#define NR 6
#define RN (NR * NTOT)

// ---------------------------------------------------------------------------
// Scratch (static __device__ globals; allocation-free per harness rules)
// ---------------------------------------------------------------------------
__device__ unsigned g_xbh[(size_t)NTOT * 64];   // packed hi: proj output (K=128)
__device__ unsigned g_xbl[(size_t)NTOT * 64];   // packed lo
__device__ unsigned g_xt1h[(size_t)NTOT * 192]; // layer1 transform, fp16 half2 [N][384]
__device__ float    g_agg1[(size_t)NTOT * 64];  // layer1 accumulator / h1 (fp32)
__device__ unsigned g_xt2h[(size_t)NTOT * 48];  // layer2 transform, fp16 half2 [N][96]
__device__ float    g_agg2[(size_t)NTOT * 16];  // layer2 accumulator / h2 (fp32)
__device__ int   g_cnt[RN];                     // per (r,dst) edge counts
__device__ int   g_off[RN];                     // segment base slot
__device__ int   g_cur[RN];                     // fill cursors
__device__ int   g_psrc[NE];                    // src node per slot (CSR payload)
__device__ int   g_total;                       // slot allocator
__device__ float g_W1[448 * 128];               // fp32 [n][k] (intermediate)
__device__ float g_W2[112 * 64];
// packed weights (hi/lo half2 words, permuted fragment layout)
__device__ unsigned g_w0h[128 * 128], g_w0l[128 * 128];   // lin_w0: 128x256
__device__ unsigned g_w1h[128 * 256], g_w1l[128 * 256];   // lin_w1: 128x512
__device__ unsigned g_w2h[128 * 64],  g_w2l[128 * 64];    // lin_w2: 128x128
__device__ unsigned g_W1h[448 * 64],  g_W1l[448 * 64];    // W1: 448x128
__device__ unsigned g_W2h[112 * 32],  g_W2l[112 * 32];    // W2: 112x64

// permuted half2-word index within a 32-col k-tile (kk even, in [0,32))
__device__ __forceinline__ int permw(int kk) {
    int c = kk >> 2;
    int idx0 = 8 * (c & 1) + 2 * (c >> 2) + ((c >> 1) & 1);
    return idx0 + ((kk >> 1) & 1) * 4;
}

// ---------------------------------------------------------------------------
// Graph preprocessing: counts -> segment offsets -> CSR fill
// ---------------------------------------------------------------------------
__global__ void zero_cnt_kernel() {
    int i = blockIdx.x * blockDim.x + threadIdx.x;
    if (i == 0) g_total = 0;
    if (i < RN) g_cnt[i] = 0;
}

__global__ void count_kernel(const int* __restrict__ dst, const int* __restrict__ et) {
    int e = blockIdx.x * blockDim.x + threadIdx.x;
    if (e < NE) atomicAdd(&g_cnt[et[e] * NTOT + dst[e]], 1);
}

// Block-aggregated slot allocation: exclusive prefix within block, one
// atomicAdd on g_total per 256 segments.
__global__ void alloc_kernel() {
    __shared__ int warp_sums[8];
    __shared__ int block_base;
    int i = blockIdx.x * 256 + threadIdx.x;
    int lane = threadIdx.x & 31, w = threadIdx.x >> 5;
    int c = (i < RN) ? g_cnt[i] : 0;
    int x = c;
    #pragma unroll
    for (int o = 1; o < 32; o <<= 1) {
        int y = __shfl_up_sync(0xffffffffu, x, o);
        if (lane >= o) x += y;
    }
    if (lane == 31) warp_sums[w] = x;
    __syncthreads();
    if (threadIdx.x < 8) {
        int v = warp_sums[threadIdx.x];
        #pragma unroll
        for (int o = 1; o < 8; o <<= 1) {
            int y = __shfl_up_sync(0xffu, v, o);
            if ((int)threadIdx.x >= o) v += y;
        }
        warp_sums[threadIdx.x] = v;
        if (threadIdx.x == 7) block_base = atomicAdd(&g_total, v);
    }
    __syncthreads();
    int base = block_base + (w ? warp_sums[w - 1] : 0) + x - c;
    if (i < RN) { g_off[i] = base; g_cur[i] = base; }
}

__global__ void fill_kernel(const int* __restrict__ ei, const int* __restrict__ et) {
    int e = blockIdx.x * blockDim.x + threadIdx.x;
    if (e >= NE) return;
    int s = ei[e];
    int d = ei[NE + e];
    int r = et[e];
    int pos = atomicAdd(&g_cur[r * NTOT + d], 1);
    g_psrc[pos] = s;
}

// ---------------------------------------------------------------------------
// Fused weight prep: build W1 and W2 fp32 in one launch
// ---------------------------------------------------------------------------
__global__ void build_w12(const float* __restrict__ comp1, const float* __restrict__ bases1,
                          const float* __restrict__ root1,
                          const float* __restrict__ comp2, const float* __restrict__ bases2,
                          const float* __restrict__ root2) {
    int idx = blockIdx.x * blockDim.x + threadIdx.x;
    if (idx < 448 * 128) {
        int n = idx >> 7, k = idx & 127;
        float v;
        if (n < 384) {
            int r = n >> 6, o = n & 63;
            v = 0.0f;
            for (int b = 0; b < 30; b++)
                v += comp1[r * 30 + b] * bases1[((size_t)b * 128 + k) * 64 + o];
        } else {
            v = root1[k * 64 + (n - 384)];
        }
        g_W1[idx] = v;
    } else {
        int idx2 = idx - 448 * 128;
        if (idx2 >= 112 * 64) return;
        int n = idx2 >> 6, k = idx2 & 63;
        float v;
        if (n < 96) {
            int r = n >> 4, o = n & 15;
            v = 0.0f;
            for (int b = 0; b < 30; b++)
                v += comp2[r * 30 + b] * bases2[((size_t)b * 64 + k) * 16 + o];
        } else {
            v = root2[k * 16 + (n - 96)];
        }
        g_W2[idx2] = v;
    }
}

// fp32 [Nrows][K] -> packed hi/lo half2 words in permuted fragment layout
__device__ __forceinline__ void splitpack_one(const float* __restrict__ src,
                                              unsigned* __restrict__ hi,
                                              unsigned* __restrict__ lo,
                                              int K, int w) {
    int wpr = K >> 1;
    int row = w / wpr, kp = w - row * wpr;
    int k = kp * 2;
    float v0 = src[(size_t)row * K + k];
    float v1 = src[(size_t)row * K + k + 1];
    __half h0 = __float2half_rn(v0), h1 = __float2half_rn(v1);
    __half l0 = __float2half_rn(v0 - __half2float(h0));
    __half l1 = __float2half_rn(v1 - __half2float(h1));
    __half2 hh = __halves2half2(h0, h1);
    __half2 ll = __halves2half2(l0, l1);
    int widx = row * wpr + ((k >> 5) << 4) + permw(k & 31);
    hi[widx] = *(unsigned*)&hh;
    lo[widx] = *(unsigned*)&ll;
}

// Fused splitpack over all 5 weight tensors (word counts: 16384/32768/8192/28672/3584)
#define SP0 16384
#define SP1 (SP0 + 32768)
#define SP2 (SP1 + 8192)
#define SP3 (SP2 + 28672)
#define SP4 (SP3 + 3584)
__global__ void splitpack_all(const float* __restrict__ lw0, const float* __restrict__ lw1,
                              const float* __restrict__ lw2) {
    int w = blockIdx.x * blockDim.x + threadIdx.x;
    if (w < SP0)      splitpack_one(lw0,  g_w0h, g_w0l, 256, w);
    else if (w < SP1) splitpack_one(lw1,  g_w1h, g_w1l, 512, w - SP0);
    else if (w < SP2) splitpack_one(lw2,  g_w2h, g_w2l, 128, w - SP1);
    else if (w < SP3) splitpack_one(g_W1, g_W1h, g_W1l, 128, w - SP2);
    else if (w < SP4) splitpack_one(g_W2, g_W2h, g_W2l, 64,  w - SP3);
}

// ---------------------------------------------------------------------------
// FP16x3 split-precision tensor-core GEMM core (templated).
// Double-buffered smem, ONE __syncthreads per 32-k tile (R12 design).
// ---------------------------------------------------------------------------
__device__ __forceinline__ void mma_fp16(float* c, unsigned a0, unsigned a1,
                                         unsigned a2, unsigned a3,
                                         unsigned b0, unsigned b1) {
    asm volatile(
        "mma.sync.aligned.m16n8k16.row.col.f32.f16.f16.f32 "
        "{%0,%1,%2,%3}, {%4,%5,%6,%7}, {%8,%9}, {%0,%1,%2,%3};"
        : "+f"(c[0]), "+f"(c[1]), "+f"(c[2]), "+f"(c[3])
        : "r"(a0), "r"(a1), "r"(a2), "r"(a3), "r"(b0), "r"(b1));
}

__device__ __forceinline__ void mma_x3(float* c,
                                       const uint4& ah0, const uint4& ah1,
                                       const uint4& al0, const uint4& al1,
                                       const uint4& bh,  const uint4& bl) {
    mma_fp16(c, ah0.x, ah1.x, ah0.y, ah1.y, bh.x, bh.y);
    mma_fp16(c, ah0.x, ah1.x, ah0.y, ah1.y, bl.x, bl.y);
    mma_fp16(c, al0.x, al1.x, al0.y, al1.y, bh.x, bh.y);
    mma_fp16(c, ah0.z, ah1.z, ah0.w, ah1.w, bh.z, bh.w);
    mma_fp16(c, ah0.z, ah1.z, ah0.w, ah1.w, bl.z, bl.w);
    mma_fp16(c, al0.z, al1.z, al0.w, al1.w, bh.z, bh.w);
}

__device__ __forceinline__ void split_store(unsigned* hi, unsigned* lo,
                                            int row, int c, float4 v) {
    __half hx0 = __float2half_rn(v.x);
    __half hx1 = __float2half_rn(v.y);
    __half hx2 = __float2half_rn(v.z);
    __half hx3 = __float2half_rn(v.w);
    __half lx0 = __float2half_rn(v.x - __half2float(hx0));
    __half lx1 = __float2half_rn(v.y - __half2float(hx1));
    __half lx2 = __float2half_rn(v.z - __half2float(hx2));
    __half lx3 = __float2half_rn(v.w - __half2float(hx3));
    int idx0 = 8 * (c & 1) + 2 * (c >> 2) + ((c >> 1) & 1);
    __half2 h01 = __halves2half2(hx0, hx1);
    __half2 h23 = __halves2half2(hx2, hx3);
    __half2 l01 = __halves2half2(lx0, lx1);
    __half2 l23 = __halves2half2(lx2, lx3);
    hi[row * 16 + idx0]     = *(unsigned*)&h01;
    hi[row * 16 + idx0 + 4] = *(unsigned*)&h23;
    lo[row * 16 + idx0]     = *(unsigned*)&l01;
    lo[row * 16 + idx0 + 4] = *(unsigned*)&l23;
}

template<int TBM, int TBN, bool APACK, int EPI>
__device__ __forceinline__ void gemm_core(
    const float* __restrict__ A,
    const unsigned* __restrict__ Ahw, const unsigned* __restrict__ Alw,
    const unsigned* __restrict__ Bhw, const unsigned* __restrict__ Blw,
    int M, int N, int K, int bm, int bn,
    int n1, const float* __restrict__ b1,
    float* __restrict__ C2, const float* __restrict__ b2,
    unsigned* __restrict__ Oh, unsigned* __restrict__ Ol) {

    __shared__ unsigned Ahi[2][TBM * 16], Alo[2][TBM * 16];
    __shared__ unsigned Bhi[2][TBN * 16], Blo[2][TBN * 16];

    constexpr int WMS = TBM / 32;
    constexpr int API = APACK ? (TBM * 4) / 256 : 1;
    constexpr int AFI = APACK ? 1 : (TBM * 8) / 256;
    constexpr int BPI = (TBN * 4) / 256;

    const int tid = threadIdx.x;
    const int wid = tid >> 5;
    const int lane = tid & 31;
    const int wm = wid % WMS;
    const int wn = wid / WMS;
    const int g = lane >> 2;
    const int t = lane & 3;
    const int wpr = K >> 1;

    float acc[2][4][4];
    #pragma unroll
    for (int i = 0; i < 2; i++)
        #pragma unroll
        for (int j = 0; j < 4; j++)
            #pragma unroll
            for (int q = 0; q < 4; q++) acc[i][j][q] = 0.0f;

    const float4 z4 = make_float4(0.f, 0.f, 0.f, 0.f);
    const uint4 zu4 = make_uint4(0, 0, 0, 0);
    uint4 pah[API], pal[API];
    float4 saf[AFI];
    uint4 pbh[BPI], pbl[BPI];

    auto ldA = [&](int k0) {
        if (APACK) {
            int ktw = (k0 >> 5) << 4;
            #pragma unroll
            for (int i = 0; i < API; i++) {
                int j = tid + i * 256; int row = j >> 2, q = j & 3;
                if (bm + row < M) {
                    size_t gw = (size_t)(bm + row) * wpr + ktw + q * 4;
                    pah[i] = *(const uint4*)&Ahw[gw];
                    pal[i] = *(const uint4*)&Alw[gw];
                } else { pah[i] = zu4; pal[i] = zu4; }
            }
        } else {
            #pragma unroll
            for (int i = 0; i < AFI; i++) {
                int j = tid + i * 256; int row = j >> 3, lc = j & 7;
                saf[i] = (bm + row < M) ?
                    *(const float4*)(A + (size_t)(bm + row) * K + k0 + lc * 4) : z4;
            }
        }
    };
    auto ldB = [&](int k0) {
        int ktw = (k0 >> 5) << 4;
        #pragma unroll
        for (int i = 0; i < BPI; i++) {
            int j = tid + i * 256; int row = j >> 2, q = j & 3;
            if (bn + row < N) {
                size_t gw = (size_t)(bn + row) * wpr + ktw + q * 4;
                pbh[i] = *(const uint4*)&Bhw[gw];
                pbl[i] = *(const uint4*)&Blw[gw];
            } else { pbh[i] = zu4; pbl[i] = zu4; }
        }
    };
    auto stA = [&](int buf) {
        if (APACK) {
            #pragma unroll
            for (int i = 0; i < API; i++) {
                int j = tid + i * 256; int row = j >> 2, q = j & 3;
                *(uint4*)&Ahi[buf][row * 16 + q * 4] = pah[i];
                *(uint4*)&Alo[buf][row * 16 + q * 4] = pal[i];
            }
        } else {
            #pragma unroll
            for (int i = 0; i < AFI; i++) {
                int j = tid + i * 256;
                split_store(Ahi[buf], Alo[buf], j >> 3, j & 7, saf[i]);
            }
        }
    };
    auto stB = [&](int buf) {
        #pragma unroll
        for (int i = 0; i < BPI; i++) {
            int j = tid + i * 256; int row = j >> 2, q = j & 3;
            *(uint4*)&Bhi[buf][row * 16 + q * 4] = pbh[i];
            *(uint4*)&Blo[buf][row * 16 + q * 4] = pbl[i];
        }
    };

    // prologue: tile 0 into buffer 0
    ldA(0); ldB(0);
    stA(0); stB(0);
    __syncthreads();

    const int nk = K >> 5;
    for (int it = 0; it < nk; it++) {
        const int cur = it & 1;
        const bool more = (it + 1) < nk;
        if (more) { ldA((it + 1) << 5); ldB((it + 1) << 5); }

        uint4 bh[4], bl[4];
        #pragma unroll
        for (int nt = 0; nt < 4; nt++) {
            int cn = wn * 32 + nt * 8 + g;
            bh[nt] = *(const uint4*)&Bhi[cur][cn * 16 + t * 4];
            bl[nt] = *(const uint4*)&Blo[cur][cn * 16 + t * 4];
        }
        #pragma unroll
        for (int mt = 0; mt < 2; mt++) {
            int r = wm * 32 + mt * 16 + g;
            uint4 ah0 = *(const uint4*)&Ahi[cur][r * 16 + t * 4];
            uint4 ah1 = *(const uint4*)&Ahi[cur][(r + 8) * 16 + t * 4];
            uint4 al0 = *(const uint4*)&Alo[cur][r * 16 + t * 4];
            uint4 al1 = *(const uint4*)&Alo[cur][(r + 8) * 16 + t * 4];
            #pragma unroll
            for (int nt = 0; nt < 4; nt++)
                mma_x3(acc[mt][nt], ah0, ah1, al0, al1, bh[nt], bl[nt]);
        }
        if (more) {
            stA(cur ^ 1); stB(cur ^ 1);
            __syncthreads();
        }
    }

    // ---- epilogue: c0=C[g][2t], c1=C[g][2t+1], c2=C[g+8][2t], c3=C[g+8][2t+1]
    const int n2w = N - n1;
    #pragma unroll
    for (int mt = 0; mt < 2; mt++) {
        #pragma unroll
        for (int nt = 0; nt < 4; nt++) {
            int col = bn + wn * 32 + nt * 8 + 2 * t;
            if (col >= N) continue;
            #pragma unroll
            for (int half = 0; half < 2; half++) {
                int row = bm + wm * 32 + mt * 16 + g + half * 8;
                if (row >= M) continue;
                float v0 = acc[mt][nt][half * 2 + 0];
                float v1 = acc[mt][nt][half * 2 + 1];
                if (EPI == 1) {
                    v0 += b1[col]; v1 += b1[col + 1];
                    __half h0 = __float2half_rn(v0), h1 = __float2half_rn(v1);
                    __half l0 = __float2half_rn(v0 - __half2float(h0));
                    __half l1 = __float2half_rn(v1 - __half2float(h1));
                    __half2 hh = __halves2half2(h0, h1);
                    __half2 ll = __halves2half2(l0, l1);
                    int widx = row * (N >> 1) + ((col >> 5) << 4) + permw(col & 31);
                    Oh[widx] = *(unsigned*)&hh;
                    Ol[widx] = *(unsigned*)&ll;
                } else { // EPI == 2
                    if (col < n1) {
                        __half2 hv = __halves2half2(__float2half_rn(v0), __float2half_rn(v1));
                        Oh[(size_t)row * (n1 >> 1) + (col >> 1)] = *(unsigned*)&hv;
                    } else {
                        int cc = col - n1;
                        v0 += b2[cc]; v1 += b2[cc + 1];
                        *(float2*)(C2 + (size_t)row * n2w + cc) = make_float2(v0, v1);
                    }
                }
            }
        }
    }
}

// Fused input projections: A fp32, B packed, packed hi/lo output into g_xb.
__global__ __launch_bounds__(256, 2)
void gemm3_proj(const float* __restrict__ x0, const float* __restrict__ bb0,
                const float* __restrict__ x1, const float* __restrict__ bb1,
                const float* __restrict__ x2, const float* __restrict__ bb2,
                int T0, int T01) {
    int tile = blockIdx.y;
    const float* A; const float* bias;
    const unsigned *bh, *bl;
    int M, K, rowbase, ltile;
    if (tile < T0)       { A = x0; bias = bb0; bh = g_w0h; bl = g_w0l; M = N0; K = 256; rowbase = 0;       ltile = tile; }
    else if (tile < T01) { A = x1; bias = bb1; bh = g_w1h; bl = g_w1l; M = N1; K = 512; rowbase = N0;      ltile = tile - T0; }
    else                 { A = x2; bias = bb2; bh = g_w2h; bl = g_w2l; M = N2; K = 128; rowbase = N0 + N1; ltile = tile - T01; }
    gemm_core<64, 128, false, 1>(A, nullptr, nullptr, bh, bl,
        M, 128, K, ltile * 64, 0,
        128, bias, nullptr, nullptr,
        g_xbh + (size_t)rowbase * 64, g_xbl + (size_t)rowbase * 64);
}

// Layer 1: A packed (xb), B packed (W1); xt1 -> fp16, agg1 -> fp32 (+bias).
__global__ __launch_bounds__(256, 2)
void gemm_l1(const float* __restrict__ bias1) {
    gemm_core<128, 64, true, 2>(nullptr, g_xbh, g_xbl, g_W1h, g_W1l,
        NTOT, 448, 128, blockIdx.y * 128, blockIdx.x * 64,
        384, nullptr, g_agg1, bias1, g_xt1h, nullptr);
}

// Layer 2: A fp32 (agg1), B packed (W2); xt2 -> fp16, agg2 -> fp32 (+bias).
__global__ __launch_bounds__(256, 2)
void gemm_l2(const float* __restrict__ bias2) {
    gemm_core<128, 64, false, 2>(g_agg1, nullptr, nullptr, g_W2h, g_W2l,
        NTOT, 112, 64, blockIdx.y * 128, blockIdx.x * 64,
        96, nullptr, g_agg2, bias2, g_xt2h, nullptr);
}

// ---------------------------------------------------------------------------
// CSR segmented reduction (atomic-free aggregation)
// ---------------------------------------------------------------------------
// Layer 1: one warp per dst; lane owns cols 2*lane, 2*lane+1.
// Segment meta fetched by lanes 0..5 and broadcast; inner loop 2x unrolled.
__global__ __launch_bounds__(256)
void reduce64_kernel() {
    int warp = (blockIdx.x * 256 + threadIdx.x) >> 5;
    int lane = threadIdx.x & 31;
    if (warp >= NTOT) return;
    int d = warp;
    int n_l = 0, beg_l = 0;
    if (lane < NR) {
        int seg = lane * NTOT + d;
        n_l = g_cnt[seg];
        beg_l = g_off[seg];
    }
    float t0 = 0.f, t1 = 0.f;
    #pragma unroll
    for (int r = 0; r < NR; r++) {
        int n = __shfl_sync(0xffffffffu, n_l, r);
        if (n == 0) continue;
        int beg = __shfl_sync(0xffffffffu, beg_l, r);
        int rc = r * 32 + lane;
        float a0 = 0.f, a1 = 0.f;
        int j = 0;
        for (; j + 2 <= n; j += 2) {
            int s0 = g_psrc[beg + j];
            int s1 = g_psrc[beg + j + 1];
            unsigned h0 = g_xt1h[(size_t)s0 * 192 + rc];
            unsigned h1 = g_xt1h[(size_t)s1 * 192 + rc];
            float2 f0 = __half22float2(*(__half2*)&h0);
            float2 f1 = __half22float2(*(__half2*)&h1);
            a0 += f0.x + f1.x; a1 += f0.y + f1.y;
        }
        if (j < n) {
            int s0 = g_psrc[beg + j];
            unsigned h0 = g_xt1h[(size_t)s0 * 192 + rc];
            float2 f0 = __half22float2(*(__half2*)&h0);
            a0 += f0.x; a1 += f0.y;
        }
        float w = 1.0f / (float)n;
        t0 += a0 * w; t1 += a1 * w;
    }
    float2* p = (float2*)(g_agg1 + (size_t)d * 64 + 2 * lane);
    float2 cur = *p;
    cur.x += t0; cur.y += t1;
    *p = cur;
}

// Layer 2 + softmax fused: 8 lanes per dst (only dst < N0); each lane owns
// cols 2*l8, 2*l8+1. After reduction, softmax over the 16 row values via
// __shfl_xor within the 8-lane group; write probabilities directly to out.
__global__ __launch_bounds__(256)
void reduce16_softmax(float* __restrict__ out) {
    int tglob = blockIdx.x * 256 + threadIdx.x;
    int d = tglob >> 3;
    int l8 = tglob & 7;
    if (d >= N0) return;
    float t0 = 0.f, t1 = 0.f;
    #pragma unroll
    for (int r = 0; r < NR; r++) {
        int seg = r * NTOT + d;
        int n = g_cnt[seg];
        if (n == 0) continue;
        int beg = g_off[seg];
        int rc = r * 8 + l8;
        float a0 = 0.f, a1 = 0.f;
        int j = 0;
        for (; j + 2 <= n; j += 2) {
            int s0 = g_psrc[beg + j];
            int s1 = g_psrc[beg + j + 1];
            unsigned h0 = g_xt2h[(size_t)s0 * 48 + rc];
            unsigned h1 = g_xt2h[(size_t)s1 * 48 + rc];
            float2 f0 = __half22float2(*(__half2*)&h0);
            float2 f1 = __half22float2(*(__half2*)&h1);
            a0 += f0.x + f1.x; a1 += f0.y + f1.y;
        }
        if (j < n) {
            int s0 = g_psrc[beg + j];
            unsigned h0 = g_xt2h[(size_t)s0 * 48 + rc];
            float2 f0 = __half22float2(*(__half2*)&h0);
            a0 += f0.x; a1 += f0.y;
        }
        float w = 1.0f / (float)n;
        t0 += a0 * w; t1 += a1 * w;
    }
    float2 init = *(float2*)(g_agg2 + (size_t)d * 16 + 2 * l8);
    float v0 = init.x + t0;
    float v1 = init.y + t1;
    // softmax across the 8-lane group (16 values)
    float m = fmaxf(v0, v1);
    #pragma unroll
    for (int o = 1; o < 8; o <<= 1)
        m = fmaxf(m, __shfl_xor_sync(0xffffffffu, m, o));
    float e0 = expf(v0 - m), e1 = expf(v1 - m);
    float ssum = e0 + e1;
    #pragma unroll
    for (int o = 1; o < 8; o <<= 1)
        ssum += __shfl_xor_sync(0xffffffffu, ssum, o);
    float inv = 1.0f / ssum;
    *(float2*)(out + (size_t)d * 16 + 2 * l8) = make_float2(e0 * inv, e1 * inv);
}

// ---------------------------------------------------------------------------
// Launcher
// ---------------------------------------------------------------------------
extern "C" void kernel_launch(void* const* d_in, const int* in_sizes, int n_in,
                              void* d_out, int out_size) {
    (void)in_sizes; (void)n_in; (void)out_size;
    const float* x0     = (const float*)d_in[0];
    const float* x1     = (const float*)d_in[1];
    const float* x2     = (const float*)d_in[2];
    const float* lin_w0 = (const float*)d_in[3];
    const float* lin_b0 = (const float*)d_in[4];
    const float* lin_w1 = (const float*)d_in[5];
    const float* lin_b1 = (const float*)d_in[6];
    const float* lin_w2 = (const float*)d_in[7];
    const float* lin_b2 = (const float*)d_in[8];
    const float* bases1 = (const float*)d_in[9];
    const float* comp1  = (const float*)d_in[10];
    const float* root1  = (const float*)d_in[11];
    const float* bias1  = (const float*)d_in[12];
    const float* bases2 = (const float*)d_in[13];
    const float* comp2  = (const float*)d_in[14];
    const float* root2  = (const float*)d_in[15];
    const float* bias2  = (const float*)d_in[16];
    const int*   eidx   = (const int*)d_in[17];
    const int*   etyp   = (const int*)d_in[18];
    float* out = (float*)d_out;

    // CSR build: counts -> offsets -> slot fill (shared by both layers)
    zero_cnt_kernel<<<(RN + 255) / 256, 256>>>();
    count_kernel<<<(NE + 255) / 256, 256>>>(eidx + NE, etyp);
    alloc_kernel<<<(RN + 255) / 256, 256>>>();
    fill_kernel<<<(NE + 255) / 256, 256>>>(eidx, etyp);

    // weight prep: fused build + fused splitpack
    build_w12<<<(448 * 128 + 112 * 64 + 255) / 256, 256>>>(comp1, bases1, root1,
                                                           comp2, bases2, root2);
    splitpack_all<<<(SP4 + 255) / 256, 256>>>(lin_w0, lin_w1, lin_w2);

    // typed input projections -> packed xb (fused single launch)
    const int T0 = (N0 + 63) / 64;
    const int T1 = (N1 + 63) / 64;
    const int T2 = (N2 + 63) / 64;
    gemm3_proj<<<dim3(1, T0 + T1 + T2), 256>>>(x0, lin_b0, x1, lin_b1, x2, lin_b2,
                                               T0, T0 + T1);

    // layer 1: xt1 (fp16 relation cols) + agg1 init (root+bias), then reduce
    gemm_l1<<<dim3(7, (NTOT + 127) / 128), 256>>>(bias1);
    reduce64_kernel<<<(NTOT * 32 + 255) / 256, 256>>>();

    // layer 2: xt2 (fp16) + agg2 init, then fused reduce+softmax (output rows)
    gemm_l2<<<dim3(2, (NTOT + 127) / 128), 256>>>(bias2);
    reduce16_softmax<<<(N0 * 8 + 255) / 256, 256>>>(out);
}